// round 4
// baseline (speedup 1.0000x reference)
#include <cuda_runtime.h>

#define BT    8192          // B*T
#define DIM   256
#define NH    3
#define NNEG  128
#define PREDN (NH*DIM)      // 768

__device__ float g_allz[BT * DIM];          // normalized z table (8 MB)
__device__ float g_pred[BT * PREDN];        // unnormalized z_pred for all horizons (24 MB)
__device__ float g_row [NH * BT];           // per-row weighted losses
__device__ int   g_is64;

__constant__ int   c_k[3] = {1, 5, 21};
__constant__ float c_w[3] = {0.6004450f, 0.26852716f, 0.13102784f}; // (1/sqrt k)/tot

// ---------------------------------------------------------------------------
// Detect whether neg_idx is stored as int64 or int32.
// Values are uniform in [0, 8192). If stored int32, an int64 read combines two
// indices -> value >= 2^32 unless the high index is 0 (p = 1/8192 per read).
// ---------------------------------------------------------------------------
__global__ void detect_kernel(const long long* __restrict__ neg) {
    int ok = 1;
    for (int i = 0; i < 64; ++i) {
        unsigned long long v = (unsigned long long)neg[i];
        if (v >= (unsigned long long)BT) { ok = 0; break; }
    }
    g_is64 = ok;
}

// ---------------------------------------------------------------------------
// Normalize rows of z_seq -> g_allz. One warp per row.
// ---------------------------------------------------------------------------
__global__ __launch_bounds__(256) void norm_kernel(const float* __restrict__ z) {
    int warp = threadIdx.x >> 5;
    int lane = threadIdx.x & 31;
    int row  = blockIdx.x * 8 + warp;

    const float4* src = (const float4*)(z + (long long)row * DIM);
    float4 a = src[lane];
    float4 b = src[lane + 32];
    float s = a.x*a.x + a.y*a.y + a.z*a.z + a.w*a.w
            + b.x*b.x + b.y*b.y + b.z*b.z + b.w*b.w;
    #pragma unroll
    for (int o = 16; o; o >>= 1) s += __shfl_xor_sync(0xffffffffu, s, o);
    float inv = 1.0f / fmaxf(sqrtf(s), 1e-12f);

    float4* dst = (float4*)(g_allz + (long long)row * DIM);
    a.x *= inv; a.y *= inv; a.z *= inv; a.w *= inv;
    b.x *= inv; b.y *= inv; b.z *= inv; b.w *= inv;
    dst[lane]      = a;
    dst[lane + 32] = b;
}

// ---------------------------------------------------------------------------
// C[m][i*256+e] = sum_d Z[m][d] * preds[i][e][d]
// = Z (8192x256) @ W^T where W = preds flattened to [768][256] row-major.
// Tiles: BM=128, BN=64, BK=16; 256 threads; 8x4 micro-tile per thread.
// ---------------------------------------------------------------------------
__global__ __launch_bounds__(256) void gemm_kernel(const float* __restrict__ A,
                                                   const float* __restrict__ W) {
    __shared__ float As[16][128];
    __shared__ float Bs[16][64];

    const int tid = threadIdx.x;
    const int bn  = blockIdx.x;   // 0..11
    const int bm  = blockIdx.y;   // 0..63
    const int ty  = tid >> 4;     // 0..15
    const int tx  = tid & 15;     // 0..15

    float acc[8][4];
    #pragma unroll
    for (int q = 0; q < 8; ++q)
        #pragma unroll
        for (int r = 0; r < 4; ++r) acc[q][r] = 0.0f;

    const float* Abase = A + (long long)(bm * 128) * 256;
    const float* Wbase = W + (long long)(bn * 64)  * 256;

    for (int k0 = 0; k0 < 256; k0 += 16) {
        // load A tile (128x16 = 512 float4, 2 per thread), transpose into As
        #pragma unroll
        for (int r = 0; r < 2; ++r) {
            int u   = tid + r * 256;
            int row = u >> 2;
            int kq  = u & 3;
            float4 v = *(const float4*)(Abase + row * 256 + k0 + kq * 4);
            As[kq*4+0][row] = v.x;
            As[kq*4+1][row] = v.y;
            As[kq*4+2][row] = v.z;
            As[kq*4+3][row] = v.w;
        }
        // load B tile (64x16 = 256 float4, 1 per thread)
        {
            int row = tid >> 2;
            int kq  = tid & 3;
            float4 v = *(const float4*)(Wbase + row * 256 + k0 + kq * 4);
            Bs[kq*4+0][row] = v.x;
            Bs[kq*4+1][row] = v.y;
            Bs[kq*4+2][row] = v.z;
            Bs[kq*4+3][row] = v.w;
        }
        __syncthreads();

        #pragma unroll
        for (int kk = 0; kk < 16; ++kk) {
            float ar[8], br[4];
            #pragma unroll
            for (int q = 0; q < 8; ++q) ar[q] = As[kk][ty * 8 + q];
            #pragma unroll
            for (int r = 0; r < 4; ++r) br[r] = Bs[kk][tx * 4 + r];
            #pragma unroll
            for (int q = 0; q < 8; ++q)
                #pragma unroll
                for (int r = 0; r < 4; ++r)
                    acc[q][r] = fmaf(ar[q], br[r], acc[q][r]);
        }
        __syncthreads();
    }

    #pragma unroll
    for (int q = 0; q < 8; ++q) {
        long long row = bm * 128 + ty * 8 + q;
        float4 v = make_float4(acc[q][0], acc[q][1], acc[q][2], acc[q][3]);
        *(float4*)(g_pred + row * PREDN + bn * 64 + tx * 4) = v;
    }
}

// ---------------------------------------------------------------------------
// Per-(horizon, row) loss: one block of 256 threads per row.
//   pos_logit = (y . allz[m+k]) / (||y|| * TEMP)
//   neg_logit[j] = (allz[idx[j]] . y) / (||y|| * TEMP)
//   row = w * (logsumexp([pos, neg]) - pos) / (B*L)
// ---------------------------------------------------------------------------
__global__ __launch_bounds__(256) void loss_kernel(const void* __restrict__ negv) {
    const int gid = blockIdx.x;
    const int hi  = gid >> 13;        // horizon index
    const int n   = gid & (BT - 1);   // row within horizon

    const int k = c_k[hi];
    const int L = 512 - k;
    const int NR = 16 * L;            // B*L

    if (n >= NR) {
        if (threadIdx.x == 0) g_row[gid] = 0.0f;
        return;
    }

    const int b = n / L;
    const int l = n - b * L;
    const int m = b * 512 + l;

    __shared__ float sy[DIM];
    __shared__ float slog[129];
    __shared__ float sA[8], sB[8];
    __shared__ float sScale, sPos;

    const int tid  = threadIdx.x;
    const int warp = tid >> 5;
    const int lane = tid & 31;

    // load y and z_pos element, reduce norm^2 and pos dot
    float yv = g_pred[(long long)m * PREDN + hi * DIM + tid];
    sy[tid] = yv;
    float zv = g_allz[(long long)(m + k) * DIM + tid];
    float v1 = yv * yv;
    float v2 = yv * zv;
    #pragma unroll
    for (int o = 16; o; o >>= 1) {
        v1 += __shfl_xor_sync(0xffffffffu, v1, o);
        v2 += __shfl_xor_sync(0xffffffffu, v2, o);
    }
    if (lane == 0) { sA[warp] = v1; sB[warp] = v2; }
    __syncthreads();
    if (tid == 0) {
        float n2 = 0.0f, p = 0.0f;
        #pragma unroll
        for (int w = 0; w < 8; ++w) { n2 += sA[w]; p += sB[w]; }
        float nrm   = sqrtf(n2);
        float scale = 1.0f / (fmaxf(nrm, 1e-12f) * 0.07f);
        sScale = scale;
        float pl = p * scale;
        sPos = pl;
        slog[128] = pl;
    }
    __syncthreads();

    const float scale = sScale;

    // per-lane slice of y
    float yr[8];
    #pragma unroll
    for (int q = 0; q < 8; ++q) yr[q] = sy[lane * 8 + q];

    const int is64 = g_is64;
    const long long base = ((long long)(hi * BT + n)) * NNEG;
    const long long* neg64 = (const long long*)negv;
    const int*       neg32 = (const int*)negv;

    // each warp handles 16 negatives
    #pragma unroll 4
    for (int jj = 0; jj < 16; ++jj) {
        int j   = (jj << 3) + warp;
        int idx = is64 ? (int)neg64[base + j] : neg32[base + j];
        const float* zr = g_allz + (long long)idx * DIM + lane * 8;
        float4 a = *(const float4*)zr;
        float4 c = *(const float4*)(zr + 4);
        float d = a.x*yr[0] + a.y*yr[1] + a.z*yr[2] + a.w*yr[3]
                + c.x*yr[4] + c.y*yr[5] + c.z*yr[6] + c.w*yr[7];
        #pragma unroll
        for (int o = 16; o; o >>= 1) d += __shfl_xor_sync(0xffffffffu, d, o);
        if (lane == 0) slog[j] = d * scale;
    }
    __syncthreads();

    // logsumexp over 129 logits
    float v = (tid < 129) ? slog[tid] : -1e30f;
    float mx = v;
    #pragma unroll
    for (int o = 16; o; o >>= 1) mx = fmaxf(mx, __shfl_xor_sync(0xffffffffu, mx, o));
    if (lane == 0) sA[warp] = mx;
    __syncthreads();
    if (tid == 0) {
        float gm = sA[0];
        #pragma unroll
        for (int w = 1; w < 8; ++w) gm = fmaxf(gm, sA[w]);
        sB[0] = gm;
    }
    __syncthreads();
    float gm = sB[0];

    float e = (tid < 129) ? expf(v - gm) : 0.0f;
    #pragma unroll
    for (int o = 16; o; o >>= 1) e += __shfl_xor_sync(0xffffffffu, e, o);
    if (lane == 0) sA[warp] = e;
    __syncthreads();
    if (tid == 0) {
        float s = 0.0f;
        #pragma unroll
        for (int w = 0; w < 8; ++w) s += sA[w];
        float lse = gm + logf(s);
        g_row[gid] = c_w[hi] * (lse - sPos) / (float)NR;
    }
}

// ---------------------------------------------------------------------------
// Deterministic final reduction of NH*BT per-row losses.
// ---------------------------------------------------------------------------
__global__ __launch_bounds__(256) void reduce_kernel(float* __restrict__ out) {
    __shared__ float s[256];
    float acc = 0.0f;
    for (int i = threadIdx.x; i < NH * BT; i += 256) acc += g_row[i];
    s[threadIdx.x] = acc;
    __syncthreads();
    for (int st = 128; st; st >>= 1) {
        if (threadIdx.x < st) s[threadIdx.x] += s[threadIdx.x + st];
        __syncthreads();
    }
    if (threadIdx.x == 0) out[0] = s[0];
}

// ---------------------------------------------------------------------------
extern "C" void kernel_launch(void* const* d_in, const int* in_sizes, int n_in,
                              void* d_out, int out_size) {
    const float* z_seq = (const float*)d_in[0];   // (16,512,256) f32
    const float* preds = (const float*)d_in[1];   // (3,256,256)  f32
    const void*  neg   = d_in[2];                 // (3,8192,128) int32 or int64

    detect_kernel<<<1, 1>>>((const long long*)neg);
    norm_kernel<<<BT / 8, 256>>>(z_seq);
    gemm_kernel<<<dim3(PREDN / 64, BT / 128), 256>>>(z_seq, preds);
    loss_kernel<<<NH * BT, 256>>>(neg);
    reduce_kernel<<<1, 256>>>((float*)d_out);
}

// round 6
// speedup vs baseline: 1.3471x; 1.3471x over previous
#include <cuda_runtime.h>
#include <cuda_bf16.h>

#define BT    8192          // B*T
#define DIM   256
#define NH    3
#define NNEG  128
#define PREDN (NH*DIM)      // 768

__device__ float          g_allz  [BT * DIM];   // normalized z table, fp32 (8 MB) — pos logits
__device__ __nv_bfloat16  g_allzbf[BT * DIM];   // normalized z table, bf16 (4 MB) — neg gathers
__device__ float          g_pred  [BT * PREDN]; // unnormalized z_pred for all horizons (24 MB)
__device__ float          g_row   [NH * BT];    // per-row weighted losses
__device__ int            g_is64;

__constant__ int   c_k[3] = {1, 5, 21};
__constant__ float c_w[3] = {0.6004450f, 0.26852716f, 0.13102784f}; // (1/sqrt k)/tot

// --- zero-cost punning helpers (nvcc rejects __builtin_bit_cast on bf162) ---
__device__ __forceinline__ unsigned bf2_to_u32(__nv_bfloat162 v) {
    union { __nv_bfloat162 b; unsigned u; } c; c.b = v; return c.u;
}
__device__ __forceinline__ float2 u32_to_f2(unsigned v) {
    union { unsigned u; __nv_bfloat162 b; } c; c.u = v;
    return __bfloat1622float2(c.b);
}

// ---------------------------------------------------------------------------
// Detect whether neg_idx is stored as int64 or int32.
// Values are uniform in [0, 8192). If stored int32, an int64 read combines two
// indices -> value >= 2^32 unless the high index is 0 (p = 1/8192 per read).
// ---------------------------------------------------------------------------
__global__ void detect_kernel(const long long* __restrict__ neg) {
    int ok = 1;
    for (int i = 0; i < 64; ++i) {
        unsigned long long v = (unsigned long long)neg[i];
        if (v >= (unsigned long long)BT) { ok = 0; break; }
    }
    g_is64 = ok;
}

// ---------------------------------------------------------------------------
// Normalize rows of z_seq -> g_allz (fp32) and g_allzbf (bf16). 1 warp / row.
// ---------------------------------------------------------------------------
__global__ __launch_bounds__(256) void norm_kernel(const float* __restrict__ z) {
    int warp = threadIdx.x >> 5;
    int lane = threadIdx.x & 31;
    int row  = blockIdx.x * 8 + warp;

    const float4* src = (const float4*)(z + (long long)row * DIM);
    float4 a = src[lane];
    float4 b = src[lane + 32];
    float s = a.x*a.x + a.y*a.y + a.z*a.z + a.w*a.w
            + b.x*b.x + b.y*b.y + b.z*b.z + b.w*b.w;
    #pragma unroll
    for (int o = 16; o; o >>= 1) s += __shfl_xor_sync(0xffffffffu, s, o);
    float inv = 1.0f / fmaxf(sqrtf(s), 1e-12f);

    a.x *= inv; a.y *= inv; a.z *= inv; a.w *= inv;
    b.x *= inv; b.y *= inv; b.z *= inv; b.w *= inv;

    float4* dst = (float4*)(g_allz + (long long)row * DIM);
    dst[lane]      = a;
    dst[lane + 32] = b;

    // bf16 copy, same element positions: floats [4*lane,4*lane+4) and +128
    __nv_bfloat16* bd = g_allzbf + (long long)row * DIM;
    uint2 pa, pb;
    pa.x = bf2_to_u32(__floats2bfloat162_rn(a.x, a.y));
    pa.y = bf2_to_u32(__floats2bfloat162_rn(a.z, a.w));
    pb.x = bf2_to_u32(__floats2bfloat162_rn(b.x, b.y));
    pb.y = bf2_to_u32(__floats2bfloat162_rn(b.z, b.w));
    *(uint2*)(bd + 4 * lane)       = pa;
    *(uint2*)(bd + 128 + 4 * lane) = pb;
}

// ---------------------------------------------------------------------------
// C[m][i*256+e] = sum_d Z[m][d] * preds[i][e][d]
// Tiles: BM=128, BN=64, BK=16; 256 threads; 8x4 micro-tile per thread.
// ---------------------------------------------------------------------------
__global__ __launch_bounds__(256) void gemm_kernel(const float* __restrict__ A,
                                                   const float* __restrict__ W) {
    __shared__ float As[16][128];
    __shared__ float Bs[16][64];

    const int tid = threadIdx.x;
    const int bn  = blockIdx.x;   // 0..11
    const int bm  = blockIdx.y;   // 0..63
    const int ty  = tid >> 4;     // 0..15
    const int tx  = tid & 15;     // 0..15

    float acc[8][4];
    #pragma unroll
    for (int q = 0; q < 8; ++q)
        #pragma unroll
        for (int r = 0; r < 4; ++r) acc[q][r] = 0.0f;

    const float* Abase = A + (long long)(bm * 128) * 256;
    const float* Wbase = W + (long long)(bn * 64)  * 256;

    for (int k0 = 0; k0 < 256; k0 += 16) {
        #pragma unroll
        for (int r = 0; r < 2; ++r) {
            int u   = tid + r * 256;
            int row = u >> 2;
            int kq  = u & 3;
            float4 v = *(const float4*)(Abase + row * 256 + k0 + kq * 4);
            As[kq*4+0][row] = v.x;
            As[kq*4+1][row] = v.y;
            As[kq*4+2][row] = v.z;
            As[kq*4+3][row] = v.w;
        }
        {
            int row = tid >> 2;
            int kq  = tid & 3;
            float4 v = *(const float4*)(Wbase + row * 256 + k0 + kq * 4);
            Bs[kq*4+0][row] = v.x;
            Bs[kq*4+1][row] = v.y;
            Bs[kq*4+2][row] = v.z;
            Bs[kq*4+3][row] = v.w;
        }
        __syncthreads();

        #pragma unroll
        for (int kk = 0; kk < 16; ++kk) {
            float ar[8], br[4];
            #pragma unroll
            for (int q = 0; q < 8; ++q) ar[q] = As[kk][ty * 8 + q];
            #pragma unroll
            for (int r = 0; r < 4; ++r) br[r] = Bs[kk][tx * 4 + r];
            #pragma unroll
            for (int q = 0; q < 8; ++q)
                #pragma unroll
                for (int r = 0; r < 4; ++r)
                    acc[q][r] = fmaf(ar[q], br[r], acc[q][r]);
        }
        __syncthreads();
    }

    #pragma unroll
    for (int q = 0; q < 8; ++q) {
        long long row = bm * 128 + ty * 8 + q;
        float4 v = make_float4(acc[q][0], acc[q][1], acc[q][2], acc[q][3]);
        *(float4*)(g_pred + row * PREDN + bn * 64 + tx * 4) = v;
    }
}

// ---------------------------------------------------------------------------
// Per-(horizon, row) loss: one block of 256 threads per row.
// Negative gathers read the bf16 table (half the L1 bytes); pos stays fp32.
// ---------------------------------------------------------------------------
__global__ __launch_bounds__(256) void loss_kernel(const void* __restrict__ negv) {
    const int gid = blockIdx.x;
    const int hi  = gid >> 13;        // horizon index
    const int n   = gid & (BT - 1);   // row within horizon

    const int k = c_k[hi];
    const int L = 512 - k;
    const int NR = 16 * L;            // B*L

    if (n >= NR) {
        if (threadIdx.x == 0) g_row[gid] = 0.0f;
        return;
    }

    const int b = n / L;
    const int l = n - b * L;
    const int m = b * 512 + l;

    __shared__ float sy[DIM];
    __shared__ float slog[129];
    __shared__ float sA[8], sB[8];
    __shared__ float sScale, sPos;

    const int tid  = threadIdx.x;
    const int warp = tid >> 5;
    const int lane = tid & 31;

    // load y and fp32 z_pos element, reduce norm^2 and pos dot
    float yv = g_pred[(long long)m * PREDN + hi * DIM + tid];
    sy[tid] = yv;
    float zv = g_allz[(long long)(m + k) * DIM + tid];
    float v1 = yv * yv;
    float v2 = yv * zv;
    #pragma unroll
    for (int o = 16; o; o >>= 1) {
        v1 += __shfl_xor_sync(0xffffffffu, v1, o);
        v2 += __shfl_xor_sync(0xffffffffu, v2, o);
    }
    if (lane == 0) { sA[warp] = v1; sB[warp] = v2; }
    __syncthreads();
    if (tid == 0) {
        float n2 = 0.0f, p = 0.0f;
        #pragma unroll
        for (int w = 0; w < 8; ++w) { n2 += sA[w]; p += sB[w]; }
        float nrm   = sqrtf(n2);
        float scale = 1.0f / (fmaxf(nrm, 1e-12f) * 0.07f);
        sScale = scale;
        float pl = p * scale;
        sPos = pl;
        slog[128] = pl;
    }
    __syncthreads();

    const float scale = sScale;

    // per-lane slice of y (8 contiguous elements)
    float yr[8];
    #pragma unroll
    for (int q = 0; q < 8; ++q) yr[q] = sy[lane * 8 + q];

    const int is64 = g_is64;
    const long long base = ((long long)(hi * BT + n)) * NNEG;
    const long long* neg64 = (const long long*)negv;
    const int*       neg32 = (const int*)negv;

    // each warp handles 16 negatives; 8 bf16 (16 B) per lane per row
    #pragma unroll 4
    for (int jj = 0; jj < 16; ++jj) {
        int j   = (jj << 3) + warp;
        int idx = is64 ? (int)neg64[base + j] : neg32[base + j];
        uint4 u = *(const uint4*)(g_allzbf + (long long)idx * DIM + lane * 8);
        float2 f0 = u32_to_f2(u.x);
        float2 f1 = u32_to_f2(u.y);
        float2 f2 = u32_to_f2(u.z);
        float2 f3 = u32_to_f2(u.w);
        float d = f0.x*yr[0] + f0.y*yr[1] + f1.x*yr[2] + f1.y*yr[3]
                + f2.x*yr[4] + f2.y*yr[5] + f3.x*yr[6] + f3.y*yr[7];
        #pragma unroll
        for (int o = 16; o; o >>= 1) d += __shfl_xor_sync(0xffffffffu, d, o);
        if (lane == 0) slog[j] = d * scale;
    }
    __syncthreads();

    // logsumexp over 129 logits
    float v = (tid < 129) ? slog[tid] : -1e30f;
    float mx = v;
    #pragma unroll
    for (int o = 16; o; o >>= 1) mx = fmaxf(mx, __shfl_xor_sync(0xffffffffu, mx, o));
    if (lane == 0) sA[warp] = mx;
    __syncthreads();
    if (tid == 0) {
        float gm = sA[0];
        #pragma unroll
        for (int w = 1; w < 8; ++w) gm = fmaxf(gm, sA[w]);
        sB[0] = gm;
    }
    __syncthreads();
    float gm = sB[0];

    float e = (tid < 129) ? expf(v - gm) : 0.0f;
    #pragma unroll
    for (int o = 16; o; o >>= 1) e += __shfl_xor_sync(0xffffffffu, e, o);
    if (lane == 0) sA[warp] = e;
    __syncthreads();
    if (tid == 0) {
        float s = 0.0f;
        #pragma unroll
        for (int w = 0; w < 8; ++w) s += sA[w];
        float lse = gm + logf(s);
        g_row[gid] = c_w[hi] * (lse - sPos) / (float)NR;
    }
}

// ---------------------------------------------------------------------------
// Deterministic final reduction of NH*BT per-row losses.
// ---------------------------------------------------------------------------
__global__ __launch_bounds__(256) void reduce_kernel(float* __restrict__ out) {
    __shared__ float s[256];
    float acc = 0.0f;
    for (int i = threadIdx.x; i < NH * BT; i += 256) acc += g_row[i];
    s[threadIdx.x] = acc;
    __syncthreads();
    for (int st = 128; st; st >>= 1) {
        if (threadIdx.x < st) s[threadIdx.x] += s[threadIdx.x + st];
        __syncthreads();
    }
    if (threadIdx.x == 0) out[0] = s[0];
}

// ---------------------------------------------------------------------------
extern "C" void kernel_launch(void* const* d_in, const int* in_sizes, int n_in,
                              void* d_out, int out_size) {
    const float* z_seq = (const float*)d_in[0];   // (16,512,256) f32
    const float* preds = (const float*)d_in[1];   // (3,256,256)  f32
    const void*  neg   = d_in[2];                 // (3,8192,128) int32 or int64

    detect_kernel<<<1, 1>>>((const long long*)neg);
    norm_kernel<<<BT / 8, 256>>>(z_seq);
    gemm_kernel<<<dim3(PREDN / 64, BT / 128), 256>>>(z_seq, preds);
    loss_kernel<<<NH * BT, 256>>>(neg);
    reduce_kernel<<<1, 256>>>((float*)d_out);
}

// round 8
// speedup vs baseline: 1.7251x; 1.2807x over previous
#include <cuda_runtime.h>
#include <cuda_fp16.h>

#define BT    8192          // B*T
#define DIM   256
#define NH    3
#define NNEG  128
#define PREDN (NH*DIM)      // 768

__device__ float         g_allz [BT * DIM];    // normalized z table, fp32 (8 MB) — pos logits
__device__ unsigned char g_allz8[BT * DIM];    // normalized z table, e4m3 (2 MB) — neg gathers
__device__ float         g_pred [BT * PREDN];  // unnormalized z_pred for all horizons (24 MB)
__device__ float         g_row  [NH * BT];     // per-row weighted losses
__device__ int           g_is64;

__constant__ int   c_k[3] = {1, 5, 21};
__constant__ float c_w[3] = {0.6004450f, 0.26852716f, 0.13102784f}; // (1/sqrt k)/tot

// ---- helpers -------------------------------------------------------------
__device__ __forceinline__ float warp_sum(float v) {          // 32-lane butterfly
    #pragma unroll
    for (int o = 16; o; o >>= 1) v += __shfl_xor_sync(0xffffffffu, v, o);
    return v;
}
// two fp32 -> packed e4m3x2 (byte0 = lo)
__device__ __forceinline__ unsigned short f2_to_e4m3x2(float lo, float hi) {
    unsigned short s;
    asm("cvt.rn.satfinite.e4m3x2.f32 %0, %1, %2;" : "=h"(s) : "f"(hi), "f"(lo));
    return s;
}
// 4 packed e4m3 (one u32 word) -> two half2 (a0 = elems 0,1; a1 = elems 2,3)
__device__ __forceinline__ void f8x4_to_h2(unsigned w, __half2& a0, __half2& a1) {
    unsigned r0, r1;
    asm("{\n\t.reg .b16 lo, hi;\n\t"
        "mov.b32 {lo, hi}, %2;\n\t"
        "cvt.rn.f16x2.e4m3x2 %0, lo;\n\t"
        "cvt.rn.f16x2.e4m3x2 %1, hi;\n\t}"
        : "=r"(r0), "=r"(r1) : "r"(w));
    a0 = *reinterpret_cast<__half2*>(&r0);
    a1 = *reinterpret_cast<__half2*>(&r1);
}
__device__ __forceinline__ __half2 u32_as_h2(unsigned w) {
    return *reinterpret_cast<__half2*>(&w);
}

// ---------------------------------------------------------------------------
// Detect whether neg_idx is stored as int64 or int32.
// ---------------------------------------------------------------------------
__global__ void detect_kernel(const long long* __restrict__ neg) {
    int ok = 1;
    for (int i = 0; i < 64; ++i) {
        unsigned long long v = (unsigned long long)neg[i];
        if (v >= (unsigned long long)BT) { ok = 0; break; }
    }
    g_is64 = ok;
}

// ---------------------------------------------------------------------------
// Normalize rows of z_seq -> g_allz (fp32) and g_allz8 (e4m3). 1 warp / row.
// ---------------------------------------------------------------------------
__global__ __launch_bounds__(256) void norm_kernel(const float* __restrict__ z) {
    int warp = threadIdx.x >> 5;
    int lane = threadIdx.x & 31;
    int row  = blockIdx.x * 8 + warp;

    const float4* src = (const float4*)(z + (long long)row * DIM);
    float4 a = src[lane];
    float4 b = src[lane + 32];
    float s = a.x*a.x + a.y*a.y + a.z*a.z + a.w*a.w
            + b.x*b.x + b.y*b.y + b.z*b.z + b.w*b.w;
    s = warp_sum(s);
    float inv = 1.0f / fmaxf(sqrtf(s), 1e-12f);

    a.x *= inv; a.y *= inv; a.z *= inv; a.w *= inv;
    b.x *= inv; b.y *= inv; b.z *= inv; b.w *= inv;

    float4* dst = (float4*)(g_allz + (long long)row * DIM);
    dst[lane]      = a;
    dst[lane + 32] = b;

    // fp8 copy: lane covers elems [4*lane,4*lane+4) and [128+4*lane, ...)
    unsigned* r8 = (unsigned*)(g_allz8 + (long long)row * DIM);
    unsigned w0 = (unsigned)f2_to_e4m3x2(a.x, a.y) | ((unsigned)f2_to_e4m3x2(a.z, a.w) << 16);
    unsigned w1 = (unsigned)f2_to_e4m3x2(b.x, b.y) | ((unsigned)f2_to_e4m3x2(b.z, b.w) << 16);
    r8[lane]      = w0;
    r8[32 + lane] = w1;
}

// ---------------------------------------------------------------------------
// C[m][i*256+e] = sum_d Z[m][d] * preds[i][e][d]
// Tiles: BM=128, BN=64, BK=16; 256 threads; 8x4 micro-tile per thread.
// ---------------------------------------------------------------------------
__global__ __launch_bounds__(256) void gemm_kernel(const float* __restrict__ A,
                                                   const float* __restrict__ W) {
    __shared__ float As[16][128];
    __shared__ float Bs[16][64];

    const int tid = threadIdx.x;
    const int bn  = blockIdx.x;
    const int bm  = blockIdx.y;
    const int ty  = tid >> 4;
    const int tx  = tid & 15;

    float acc[8][4];
    #pragma unroll
    for (int q = 0; q < 8; ++q)
        #pragma unroll
        for (int r = 0; r < 4; ++r) acc[q][r] = 0.0f;

    const float* Abase = A + (long long)(bm * 128) * 256;
    const float* Wbase = W + (long long)(bn * 64)  * 256;

    for (int k0 = 0; k0 < 256; k0 += 16) {
        #pragma unroll
        for (int r = 0; r < 2; ++r) {
            int u   = tid + r * 256;
            int row = u >> 2;
            int kq  = u & 3;
            float4 v = *(const float4*)(Abase + row * 256 + k0 + kq * 4);
            As[kq*4+0][row] = v.x;
            As[kq*4+1][row] = v.y;
            As[kq*4+2][row] = v.z;
            As[kq*4+3][row] = v.w;
        }
        {
            int row = tid >> 2;
            int kq  = tid & 3;
            float4 v = *(const float4*)(Wbase + row * 256 + k0 + kq * 4);
            Bs[kq*4+0][row] = v.x;
            Bs[kq*4+1][row] = v.y;
            Bs[kq*4+2][row] = v.z;
            Bs[kq*4+3][row] = v.w;
        }
        __syncthreads();

        #pragma unroll
        for (int kk = 0; kk < 16; ++kk) {
            float ar[8], br[4];
            #pragma unroll
            for (int q = 0; q < 8; ++q) ar[q] = As[kk][ty * 8 + q];
            #pragma unroll
            for (int r = 0; r < 4; ++r) br[r] = Bs[kk][tx * 4 + r];
            #pragma unroll
            for (int q = 0; q < 8; ++q)
                #pragma unroll
                for (int r = 0; r < 4; ++r)
                    acc[q][r] = fmaf(ar[q], br[r], acc[q][r]);
        }
        __syncthreads();
    }

    #pragma unroll
    for (int q = 0; q < 8; ++q) {
        long long row = bm * 128 + ty * 8 + q;
        float4 v = make_float4(acc[q][0], acc[q][1], acc[q][2], acc[q][3]);
        *(float4*)(g_pred + row * PREDN + bn * 64 + tx * 4) = v;
    }
}

// ---------------------------------------------------------------------------
// Per-(horizon, row) loss: one block of 256 threads per row.
// Negatives: fp8 table, 8 lanes per negative (4 negatives per warp-pass),
// f16x2 dot against the pre-normalized f16 y, 3-step segment butterfly.
// ---------------------------------------------------------------------------
__global__ __launch_bounds__(256) void loss_kernel(const void* __restrict__ negv) {
    const int gid = blockIdx.x;
    const int hi  = gid >> 13;
    const int n   = gid & (BT - 1);

    const int k = c_k[hi];
    const int L = 512 - k;
    const int NR = 16 * L;

    if (n >= NR) {
        if (threadIdx.x == 0) g_row[gid] = 0.0f;
        return;
    }

    const int b = n / L;
    const int l = n - b * L;
    const int m = b * 512 + l;

    __shared__ __half sy_h[DIM];          // unit-normalized y, f16
    __shared__ float  slog[129];
    __shared__ float  sA[8], sB[8];
    __shared__ float  sScale, sPos;

    const int tid  = threadIdx.x;
    const int warp = tid >> 5;
    const int lane = tid & 31;
    const int seg  = lane >> 3;           // 0..3 : which negative in the quad
    const int c    = lane & 7;            // 0..7 : 16-byte chunk within row half

    // ---- phase 1: norm(y), pos logit (fp32) ----
    float yv = g_pred[(long long)m * PREDN + hi * DIM + tid];
    float zv = g_allz[(long long)(m + k) * DIM + tid];
    float v1 = warp_sum(yv * yv);
    float v2 = warp_sum(yv * zv);
    if (lane == 0) { sA[warp] = v1; sB[warp] = v2; }
    __syncthreads();
    if (tid == 0) {
        float n2 = 0.0f, p = 0.0f;
        #pragma unroll
        for (int w = 0; w < 8; ++w) { n2 += sA[w]; p += sB[w]; }
        float nrm   = sqrtf(n2);
        float scale = 1.0f / (fmaxf(nrm, 1e-12f) * 0.07f);
        sScale = scale;
        float pl = p * scale;
        sPos = pl;
        slog[128] = pl;
    }
    __syncthreads();

    // unit-normalized y in f16 (fold 1/||y||; temp applied at logit store)
    const float invn = sScale * 0.07f;    // = 1/max(||y||,1e-12)
    sy_h[tid] = __float2half(yv * invn);
    __syncthreads();

    // lane's fixed y chunks: elems [16c,16c+16) and [16(c+8), ...)
    const uint4* syh4 = (const uint4*)sy_h;   // 8 halves per uint4
    uint4 t0 = syh4[2*c];
    uint4 t1 = syh4[2*c + 1];
    uint4 t2 = syh4[2*c + 16];
    uint4 t3 = syh4[2*c + 17];

    const int is64 = g_is64;
    const long long base = ((long long)(hi * BT + n)) * NNEG;
    const int* neg32 = (const int*)negv;  // LE low word valid for both widths

    // ---- phase 2: 128 negatives; warp w handles j in [16w,16w+16) ----
    #pragma unroll
    for (int it = 0; it < 4; ++it) {
        int j = (warp << 4) + (it << 2) + seg;
        long long o = base + j;
        int idx = neg32[is64 ? (o << 1) : o];
        const uint4* rowp = (const uint4*)(g_allz8 + ((size_t)idx << 8));
        uint4 u0 = rowp[c];        // elems [16c, 16c+16)
        uint4 u1 = rowp[c + 8];    // elems [16c+128, +16)

        __half2 acc = __float2half2_rn(0.0f);
        __half2 a0, a1;
        f8x4_to_h2(u0.x, a0, a1);
        acc = __hfma2(a0, u32_as_h2(t0.x), acc);
        acc = __hfma2(a1, u32_as_h2(t0.y), acc);
        f8x4_to_h2(u0.y, a0, a1);
        acc = __hfma2(a0, u32_as_h2(t0.z), acc);
        acc = __hfma2(a1, u32_as_h2(t0.w), acc);
        f8x4_to_h2(u0.z, a0, a1);
        acc = __hfma2(a0, u32_as_h2(t1.x), acc);
        acc = __hfma2(a1, u32_as_h2(t1.y), acc);
        f8x4_to_h2(u0.w, a0, a1);
        acc = __hfma2(a0, u32_as_h2(t1.z), acc);
        acc = __hfma2(a1, u32_as_h2(t1.w), acc);
        f8x4_to_h2(u1.x, a0, a1);
        acc = __hfma2(a0, u32_as_h2(t2.x), acc);
        acc = __hfma2(a1, u32_as_h2(t2.y), acc);
        f8x4_to_h2(u1.y, a0, a1);
        acc = __hfma2(a0, u32_as_h2(t2.z), acc);
        acc = __hfma2(a1, u32_as_h2(t2.w), acc);
        f8x4_to_h2(u1.z, a0, a1);
        acc = __hfma2(a0, u32_as_h2(t3.x), acc);
        acc = __hfma2(a1, u32_as_h2(t3.y), acc);
        f8x4_to_h2(u1.w, a0, a1);
        acc = __hfma2(a0, u32_as_h2(t3.z), acc);
        acc = __hfma2(a1, u32_as_h2(t3.w), acc);

        float d = __low2float(acc) + __high2float(acc);
        d += __shfl_xor_sync(0xffffffffu, d, 1);
        d += __shfl_xor_sync(0xffffffffu, d, 2);
        d += __shfl_xor_sync(0xffffffffu, d, 4);
        if (c == 0) slog[j] = d * 14.285714f;   // cos / TEMP
    }
    __syncthreads();

    // ---- phase 3: logsumexp over 129 logits ----
    float v = (tid < 129) ? slog[tid] : -1e30f;
    float mx = v;
    #pragma unroll
    for (int o = 16; o; o >>= 1) mx = fmaxf(mx, __shfl_xor_sync(0xffffffffu, mx, o));
    if (lane == 0) sA[warp] = mx;
    __syncthreads();
    if (tid == 0) {
        float gm = sA[0];
        #pragma unroll
        for (int w = 1; w < 8; ++w) gm = fmaxf(gm, sA[w]);
        sB[0] = gm;
    }
    __syncthreads();
    float gm = sB[0];

    float e = (tid < 129) ? expf(v - gm) : 0.0f;
    e = warp_sum(e);
    if (lane == 0) sA[warp] = e;
    __syncthreads();
    if (tid == 0) {
        float s = 0.0f;
        #pragma unroll
        for (int w = 0; w < 8; ++w) s += sA[w];
        float lse = gm + logf(s);
        g_row[gid] = c_w[hi] * (lse - sPos) / (float)NR;
    }
}

// ---------------------------------------------------------------------------
// Deterministic final reduction of NH*BT per-row losses.
// ---------------------------------------------------------------------------
__global__ __launch_bounds__(256) void reduce_kernel(float* __restrict__ out) {
    __shared__ float s[256];
    float acc = 0.0f;
    for (int i = threadIdx.x; i < NH * BT; i += 256) acc += g_row[i];
    s[threadIdx.x] = acc;
    __syncthreads();
    for (int st = 128; st; st >>= 1) {
        if (threadIdx.x < st) s[threadIdx.x] += s[threadIdx.x + st];
        __syncthreads();
    }
    if (threadIdx.x == 0) out[0] = s[0];
}

// ---------------------------------------------------------------------------
extern "C" void kernel_launch(void* const* d_in, const int* in_sizes, int n_in,
                              void* d_out, int out_size) {
    const float* z_seq = (const float*)d_in[0];   // (16,512,256) f32
    const float* preds = (const float*)d_in[1];   // (3,256,256)  f32
    const void*  neg   = d_in[2];                 // (3,8192,128) int32 or int64

    detect_kernel<<<1, 1>>>((const long long*)neg);
    norm_kernel<<<BT / 8, 256>>>(z_seq);
    gemm_kernel<<<dim3(PREDN / 64, BT / 128), 256>>>(z_seq, preds);
    loss_kernel<<<NH * BT, 256>>>(neg);
    reduce_kernel<<<1, 256>>>((float*)d_out);
}

// round 9
// speedup vs baseline: 2.1584x; 1.2511x over previous
#include <cuda_runtime.h>
#include <cuda_fp16.h>

#define BT    8192          // B*T
#define DIM   256
#define NH    3
#define NNEG  128
#define PREDN (NH*DIM)      // 768

__device__ float         g_allz [BT * DIM];    // normalized z table, fp32 (8 MB) — pos logits
__device__ unsigned char g_allz8[BT * DIM];    // normalized z table, e4m3 (2 MB) — neg gathers
__device__ float         g_pred [BT * PREDN];  // unnormalized z_pred for all horizons (24 MB)
__device__ float         g_row  [NH * BT];     // per-row weighted losses
__device__ int           g_is64;

__constant__ int   c_k[3] = {1, 5, 21};
__constant__ float c_w[3] = {0.6004450f, 0.26852716f, 0.13102784f}; // (1/sqrt k)/tot

// ---- helpers -------------------------------------------------------------
__device__ __forceinline__ float warp_sum(float v) {          // 32-lane butterfly
    #pragma unroll
    for (int o = 16; o; o >>= 1) v += __shfl_xor_sync(0xffffffffu, v, o);
    return v;
}
// two fp32 -> packed e4m3x2 (byte0 = lo)
__device__ __forceinline__ unsigned short f2_to_e4m3x2(float lo, float hi) {
    unsigned short s;
    asm("cvt.rn.satfinite.e4m3x2.f32 %0, %1, %2;" : "=h"(s) : "f"(hi), "f"(lo));
    return s;
}
// 4 packed e4m3 (one u32 word) -> two half2 (a0 = elems 0,1; a1 = elems 2,3)
__device__ __forceinline__ void f8x4_to_h2(unsigned w, __half2& a0, __half2& a1) {
    unsigned r0, r1;
    asm("{\n\t.reg .b16 lo, hi;\n\t"
        "mov.b32 {lo, hi}, %2;\n\t"
        "cvt.rn.f16x2.e4m3x2 %0, lo;\n\t"
        "cvt.rn.f16x2.e4m3x2 %1, hi;\n\t}"
        : "=r"(r0), "=r"(r1) : "r"(w));
    a0 = *reinterpret_cast<__half2*>(&r0);
    a1 = *reinterpret_cast<__half2*>(&r1);
}
__device__ __forceinline__ __half2 u32_as_h2(unsigned w) {
    return *reinterpret_cast<__half2*>(&w);
}

// ---------------------------------------------------------------------------
// Detect whether neg_idx is stored as int64 or int32.
// ---------------------------------------------------------------------------
__global__ void detect_kernel(const long long* __restrict__ neg) {
    int ok = 1;
    for (int i = 0; i < 64; ++i) {
        unsigned long long v = (unsigned long long)neg[i];
        if (v >= (unsigned long long)BT) { ok = 0; break; }
    }
    g_is64 = ok;
}

// ---------------------------------------------------------------------------
// Normalize rows of z_seq -> g_allz (fp32) and g_allz8 (e4m3). 1 warp / row.
// ---------------------------------------------------------------------------
__global__ __launch_bounds__(256) void norm_kernel(const float* __restrict__ z) {
    int warp = threadIdx.x >> 5;
    int lane = threadIdx.x & 31;
    int row  = blockIdx.x * 8 + warp;

    const float4* src = (const float4*)(z + (long long)row * DIM);
    float4 a = src[lane];
    float4 b = src[lane + 32];
    float s = a.x*a.x + a.y*a.y + a.z*a.z + a.w*a.w
            + b.x*b.x + b.y*b.y + b.z*b.z + b.w*b.w;
    s = warp_sum(s);
    float inv = 1.0f / fmaxf(sqrtf(s), 1e-12f);

    a.x *= inv; a.y *= inv; a.z *= inv; a.w *= inv;
    b.x *= inv; b.y *= inv; b.z *= inv; b.w *= inv;

    float4* dst = (float4*)(g_allz + (long long)row * DIM);
    dst[lane]      = a;
    dst[lane + 32] = b;

    unsigned* r8 = (unsigned*)(g_allz8 + (long long)row * DIM);
    unsigned w0 = (unsigned)f2_to_e4m3x2(a.x, a.y) | ((unsigned)f2_to_e4m3x2(a.z, a.w) << 16);
    unsigned w1 = (unsigned)f2_to_e4m3x2(b.x, b.y) | ((unsigned)f2_to_e4m3x2(b.z, b.w) << 16);
    r8[lane]      = w0;
    r8[32 + lane] = w1;
}

// ---------------------------------------------------------------------------
// C[m][i*256+e] = sum_d Z[m][d] * preds[i][e][d]
// Tiles: BM=128, BN=64, BK=16; 256 threads; 8x4 micro-tile per thread.
// ---------------------------------------------------------------------------
__global__ __launch_bounds__(256) void gemm_kernel(const float* __restrict__ A,
                                                   const float* __restrict__ W) {
    __shared__ float As[16][128];
    __shared__ float Bs[16][64];

    const int tid = threadIdx.x;
    const int bn  = blockIdx.x;
    const int bm  = blockIdx.y;
    const int ty  = tid >> 4;
    const int tx  = tid & 15;

    float acc[8][4];
    #pragma unroll
    for (int q = 0; q < 8; ++q)
        #pragma unroll
        for (int r = 0; r < 4; ++r) acc[q][r] = 0.0f;

    const float* Abase = A + (long long)(bm * 128) * 256;
    const float* Wbase = W + (long long)(bn * 64)  * 256;

    for (int k0 = 0; k0 < 256; k0 += 16) {
        #pragma unroll
        for (int r = 0; r < 2; ++r) {
            int u   = tid + r * 256;
            int row = u >> 2;
            int kq  = u & 3;
            float4 v = *(const float4*)(Abase + row * 256 + k0 + kq * 4);
            As[kq*4+0][row] = v.x;
            As[kq*4+1][row] = v.y;
            As[kq*4+2][row] = v.z;
            As[kq*4+3][row] = v.w;
        }
        {
            int row = tid >> 2;
            int kq  = tid & 3;
            float4 v = *(const float4*)(Wbase + row * 256 + k0 + kq * 4);
            Bs[kq*4+0][row] = v.x;
            Bs[kq*4+1][row] = v.y;
            Bs[kq*4+2][row] = v.z;
            Bs[kq*4+3][row] = v.w;
        }
        __syncthreads();

        #pragma unroll
        for (int kk = 0; kk < 16; ++kk) {
            float ar[8], br[4];
            #pragma unroll
            for (int q = 0; q < 8; ++q) ar[q] = As[kk][ty * 8 + q];
            #pragma unroll
            for (int r = 0; r < 4; ++r) br[r] = Bs[kk][tx * 4 + r];
            #pragma unroll
            for (int q = 0; q < 8; ++q)
                #pragma unroll
                for (int r = 0; r < 4; ++r)
                    acc[q][r] = fmaf(ar[q], br[r], acc[q][r]);
        }
        __syncthreads();
    }

    #pragma unroll
    for (int q = 0; q < 8; ++q) {
        long long row = bm * 128 + ty * 8 + q;
        float4 v = make_float4(acc[q][0], acc[q][1], acc[q][2], acc[q][3]);
        *(float4*)(g_pred + row * PREDN + bn * 64 + tx * 4) = v;
    }
}

// ---------------------------------------------------------------------------
// Loss: ONE WARP PER ROW — no block barriers at all.
// |logit| <= ~14.3 so exp() is safe in fp32 without max-subtraction:
// accumulate sum(exp(logit)) directly; lse = log(sum + exp(pos)).
// ---------------------------------------------------------------------------
__global__ __launch_bounds__(256, 5) void loss_kernel(const void* __restrict__ negv) {
    const int warp = threadIdx.x >> 5;
    const int lane = threadIdx.x & 31;
    const int gid  = blockIdx.x * 8 + warp;      // 0 .. 24575
    const int hi   = gid >> 13;
    const int n    = gid & (BT - 1);

    const int k = c_k[hi];
    const int L = 512 - k;
    const int NR = 16 * L;

    if (n >= NR) {
        if (lane == 0) g_row[gid] = 0.0f;
        return;
    }

    const int b = n / L;
    const int l = n - b * L;
    const int m = b * 512 + l;

    __shared__ __half sy_all[8 * DIM];           // 4 KB: per-warp f16 y
    __half* sy_h = sy_all + warp * DIM;

    // ---- phase 1: norm(y) and pos logit, fp32, warp-local ----
    const float4* yp = (const float4*)(g_pred + (long long)m * PREDN + hi * DIM);
    const float4* zp = (const float4*)(g_allz + (long long)(m + k) * DIM);
    float4 ya = yp[lane], yb = yp[lane + 32];
    float4 za = zp[lane], zb = zp[lane + 32];
    float v1 = ya.x*ya.x + ya.y*ya.y + ya.z*ya.z + ya.w*ya.w
             + yb.x*yb.x + yb.y*yb.y + yb.z*yb.z + yb.w*yb.w;
    float v2 = ya.x*za.x + ya.y*za.y + ya.z*za.z + ya.w*za.w
             + yb.x*zb.x + yb.y*zb.y + yb.z*zb.z + yb.w*zb.w;
    v1 = warp_sum(v1);
    v2 = warp_sum(v2);
    const float invn = 1.0f / fmaxf(sqrtf(v1), 1e-12f);
    const float pos  = v2 * invn * 14.285714286f;   // cos/TEMP

    // unit y in f16: lane covers elems [4*lane,4*lane+4) and [128+4*lane, ..)
    {
        __half2* sh2 = (__half2*)sy_h;
        sh2[2*lane+0]    = __floats2half2_rn(ya.x*invn, ya.y*invn);
        sh2[2*lane+1]    = __floats2half2_rn(ya.z*invn, ya.w*invn);
        sh2[64+2*lane+0] = __floats2half2_rn(yb.x*invn, yb.y*invn);
        sh2[64+2*lane+1] = __floats2half2_rn(yb.z*invn, yb.w*invn);
    }
    __syncwarp();

    // lane's fixed 32-elem y chunk: elems [32c, 32c+32)
    const int seg = lane >> 3;                   // 0..3
    const int c   = lane & 7;                    // 0..7
    const uint4* syh4 = (const uint4*)sy_h;
    uint4 t0 = syh4[4*c + 0];
    uint4 t1 = syh4[4*c + 1];
    uint4 t2 = syh4[4*c + 2];
    uint4 t3 = syh4[4*c + 3];

    const int is64 = g_is64;
    const long long base = ((long long)(hi * BT + n)) * NNEG;
    const int* neg32 = (const int*)negv;         // LE low word valid for both widths

    // ---- phase 2: 128 negatives, 4 per pass (8 lanes each) ----
    float ssum = 0.0f;
    #pragma unroll 4
    for (int pass = 0; pass < 32; ++pass) {
        int j = (pass << 2) + seg;
        long long o = base + j;
        int idx = neg32[is64 ? (o << 1) : o];
        const uint4* rowp = (const uint4*)(g_allz8 + ((size_t)idx << 8));
        uint4 u0 = rowp[2*c];                    // bytes [32c, 32c+16)
        uint4 u1 = rowp[2*c + 1];                // bytes [32c+16, 32c+32)

        __half2 acc = __float2half2_rn(0.0f);
        __half2 a0, a1;
        f8x4_to_h2(u0.x, a0, a1);
        acc = __hfma2(a0, u32_as_h2(t0.x), acc);
        acc = __hfma2(a1, u32_as_h2(t0.y), acc);
        f8x4_to_h2(u0.y, a0, a1);
        acc = __hfma2(a0, u32_as_h2(t0.z), acc);
        acc = __hfma2(a1, u32_as_h2(t0.w), acc);
        f8x4_to_h2(u0.z, a0, a1);
        acc = __hfma2(a0, u32_as_h2(t1.x), acc);
        acc = __hfma2(a1, u32_as_h2(t1.y), acc);
        f8x4_to_h2(u0.w, a0, a1);
        acc = __hfma2(a0, u32_as_h2(t1.z), acc);
        acc = __hfma2(a1, u32_as_h2(t1.w), acc);
        f8x4_to_h2(u1.x, a0, a1);
        acc = __hfma2(a0, u32_as_h2(t2.x), acc);
        acc = __hfma2(a1, u32_as_h2(t2.y), acc);
        f8x4_to_h2(u1.y, a0, a1);
        acc = __hfma2(a0, u32_as_h2(t2.z), acc);
        acc = __hfma2(a1, u32_as_h2(t2.w), acc);
        f8x4_to_h2(u1.z, a0, a1);
        acc = __hfma2(a0, u32_as_h2(t3.x), acc);
        acc = __hfma2(a1, u32_as_h2(t3.y), acc);
        f8x4_to_h2(u1.w, a0, a1);
        acc = __hfma2(a0, u32_as_h2(t3.z), acc);
        acc = __hfma2(a1, u32_as_h2(t3.w), acc);

        float d = __low2float(acc) + __high2float(acc);
        d += __shfl_xor_sync(0xffffffffu, d, 1);
        d += __shfl_xor_sync(0xffffffffu, d, 2);
        d += __shfl_xor_sync(0xffffffffu, d, 4);
        ssum += __expf(d * 14.285714286f);       // logit in [-14.5, 14.5]: safe
    }

    // combine 4 segments (values identical within a segment)
    ssum += __shfl_xor_sync(0xffffffffu, ssum, 8);
    ssum += __shfl_xor_sync(0xffffffffu, ssum, 16);

    if (lane == 0) {
        float lse = logf(ssum + expf(pos));
        g_row[gid] = c_w[hi] * (lse - pos) / (float)NR;
    }
}

// ---------------------------------------------------------------------------
// Deterministic final reduction of NH*BT per-row losses.
// ---------------------------------------------------------------------------
__global__ __launch_bounds__(256) void reduce_kernel(float* __restrict__ out) {
    __shared__ float s[256];
    float acc = 0.0f;
    for (int i = threadIdx.x; i < NH * BT; i += 256) acc += g_row[i];
    s[threadIdx.x] = acc;
    __syncthreads();
    for (int st = 128; st; st >>= 1) {
        if (threadIdx.x < st) s[threadIdx.x] += s[threadIdx.x + st];
        __syncthreads();
    }
    if (threadIdx.x == 0) out[0] = s[0];
}

// ---------------------------------------------------------------------------
extern "C" void kernel_launch(void* const* d_in, const int* in_sizes, int n_in,
                              void* d_out, int out_size) {
    const float* z_seq = (const float*)d_in[0];   // (16,512,256) f32
    const float* preds = (const float*)d_in[1];   // (3,256,256)  f32
    const void*  neg   = d_in[2];                 // (3,8192,128) int32 or int64

    detect_kernel<<<1, 1>>>((const long long*)neg);
    norm_kernel<<<BT / 8, 256>>>(z_seq);
    gemm_kernel<<<dim3(PREDN / 64, BT / 128), 256>>>(z_seq, preds);
    loss_kernel<<<NH * BT / 8, 256>>>(neg);
    reduce_kernel<<<1, 256>>>((float*)d_out);
}

// round 10
// speedup vs baseline: 2.1635x; 1.0024x over previous
#include <cuda_runtime.h>
#include <cuda_fp16.h>

#define BT    8192          // B*T
#define DIM   256
#define NH    3
#define NNEG  128
#define PREDN (NH*DIM)      // 768

__device__ float         g_allz [BT * DIM];    // normalized z table, fp32 (8 MB) — pos logits
__device__ unsigned char g_allz8[BT * DIM];    // normalized z table, e4m3 (2 MB) — neg gathers
__device__ float         g_pred [BT * PREDN];  // unnormalized z_pred for all horizons (24 MB)
__device__ float         g_row  [NH * BT];     // per-row weighted losses
__device__ int           g_is64;

__constant__ int   c_k[3] = {1, 5, 21};
__constant__ float c_w[3] = {0.6004450f, 0.26852716f, 0.13102784f}; // (1/sqrt k)/tot

// ---- helpers -------------------------------------------------------------
__device__ __forceinline__ float warp_sum(float v) {          // 32-lane butterfly
    #pragma unroll
    for (int o = 16; o; o >>= 1) v += __shfl_xor_sync(0xffffffffu, v, o);
    return v;
}
// two fp32 -> packed e4m3x2 (byte0 = lo)
__device__ __forceinline__ unsigned short f2_to_e4m3x2(float lo, float hi) {
    unsigned short s;
    asm("cvt.rn.satfinite.e4m3x2.f32 %0, %1, %2;" : "=h"(s) : "f"(hi), "f"(lo));
    return s;
}
// 4 packed e4m3 (one u32 word) -> two half2 (a0 = elems 0,1; a1 = elems 2,3)
__device__ __forceinline__ void f8x4_to_h2(unsigned w, __half2& a0, __half2& a1) {
    unsigned r0, r1;
    asm("{\n\t.reg .b16 lo, hi;\n\t"
        "mov.b32 {lo, hi}, %2;\n\t"
        "cvt.rn.f16x2.e4m3x2 %0, lo;\n\t"
        "cvt.rn.f16x2.e4m3x2 %1, hi;\n\t}"
        : "=r"(r0), "=r"(r1) : "r"(w));
    a0 = *reinterpret_cast<__half2*>(&r0);
    a1 = *reinterpret_cast<__half2*>(&r1);
}
__device__ __forceinline__ __half2 u32_as_h2(unsigned w) {
    return *reinterpret_cast<__half2*>(&w);
}

// ---------------------------------------------------------------------------
// Detect whether neg_idx is stored as int64 or int32.
// ---------------------------------------------------------------------------
__global__ void detect_kernel(const long long* __restrict__ neg) {
    int ok = 1;
    for (int i = 0; i < 64; ++i) {
        unsigned long long v = (unsigned long long)neg[i];
        if (v >= (unsigned long long)BT) { ok = 0; break; }
    }
    g_is64 = ok;
}

// ---------------------------------------------------------------------------
// Normalize rows of z_seq -> g_allz (fp32) and g_allz8 (e4m3). 1 warp / row.
// ---------------------------------------------------------------------------
__global__ __launch_bounds__(256) void norm_kernel(const float* __restrict__ z) {
    int warp = threadIdx.x >> 5;
    int lane = threadIdx.x & 31;
    int row  = blockIdx.x * 8 + warp;

    const float4* src = (const float4*)(z + (long long)row * DIM);
    float4 a = src[lane];
    float4 b = src[lane + 32];
    float s = a.x*a.x + a.y*a.y + a.z*a.z + a.w*a.w
            + b.x*b.x + b.y*b.y + b.z*b.z + b.w*b.w;
    s = warp_sum(s);
    float inv = 1.0f / fmaxf(sqrtf(s), 1e-12f);

    a.x *= inv; a.y *= inv; a.z *= inv; a.w *= inv;
    b.x *= inv; b.y *= inv; b.z *= inv; b.w *= inv;

    float4* dst = (float4*)(g_allz + (long long)row * DIM);
    dst[lane]      = a;
    dst[lane + 32] = b;

    unsigned* r8 = (unsigned*)(g_allz8 + (long long)row * DIM);
    unsigned w0 = (unsigned)f2_to_e4m3x2(a.x, a.y) | ((unsigned)f2_to_e4m3x2(a.z, a.w) << 16);
    unsigned w1 = (unsigned)f2_to_e4m3x2(b.x, b.y) | ((unsigned)f2_to_e4m3x2(b.z, b.w) << 16);
    r8[lane]      = w0;
    r8[32 + lane] = w1;
}

// ---------------------------------------------------------------------------
// C[m][i*256+e] = sum_d Z[m][d] * preds[i][e][d]
// Tiles: BM=128, BN=64, BK=16; 256 threads; 8x4 micro-tile per thread.
// ---------------------------------------------------------------------------
__global__ __launch_bounds__(256) void gemm_kernel(const float* __restrict__ A,
                                                   const float* __restrict__ W) {
    __shared__ float As[16][128];
    __shared__ float Bs[16][64];

    const int tid = threadIdx.x;
    const int bn  = blockIdx.x;
    const int bm  = blockIdx.y;
    const int ty  = tid >> 4;
    const int tx  = tid & 15;

    float acc[8][4];
    #pragma unroll
    for (int q = 0; q < 8; ++q)
        #pragma unroll
        for (int r = 0; r < 4; ++r) acc[q][r] = 0.0f;

    const float* Abase = A + (long long)(bm * 128) * 256;
    const float* Wbase = W + (long long)(bn * 64)  * 256;

    for (int k0 = 0; k0 < 256; k0 += 16) {
        #pragma unroll
        for (int r = 0; r < 2; ++r) {
            int u   = tid + r * 256;
            int row = u >> 2;
            int kq  = u & 3;
            float4 v = *(const float4*)(Abase + row * 256 + k0 + kq * 4);
            As[kq*4+0][row] = v.x;
            As[kq*4+1][row] = v.y;
            As[kq*4+2][row] = v.z;
            As[kq*4+3][row] = v.w;
        }
        {
            int row = tid >> 2;
            int kq  = tid & 3;
            float4 v = *(const float4*)(Wbase + row * 256 + k0 + kq * 4);
            Bs[kq*4+0][row] = v.x;
            Bs[kq*4+1][row] = v.y;
            Bs[kq*4+2][row] = v.z;
            Bs[kq*4+3][row] = v.w;
        }
        __syncthreads();

        #pragma unroll
        for (int kk = 0; kk < 16; ++kk) {
            float ar[8], br[4];
            #pragma unroll
            for (int q = 0; q < 8; ++q) ar[q] = As[kk][ty * 8 + q];
            #pragma unroll
            for (int r = 0; r < 4; ++r) br[r] = Bs[kk][tx * 4 + r];
            #pragma unroll
            for (int q = 0; q < 8; ++q)
                #pragma unroll
                for (int r = 0; r < 4; ++r)
                    acc[q][r] = fmaf(ar[q], br[r], acc[q][r]);
        }
        __syncthreads();
    }

    #pragma unroll
    for (int q = 0; q < 8; ++q) {
        long long row = bm * 128 + ty * 8 + q;
        float4 v = make_float4(acc[q][0], acc[q][1], acc[q][2], acc[q][3]);
        *(float4*)(g_pred + row * PREDN + bn * 64 + tx * 4) = v;
    }
}

// ---------------------------------------------------------------------------
// Loss: ONE WARP PER ROW — no block barriers at all.
// |logit| <= ~14.3 so exp() is safe in fp32 without max-subtraction:
// accumulate sum(exp(logit)) directly; lse = log(sum + exp(pos)).
// ---------------------------------------------------------------------------
__global__ __launch_bounds__(256, 5) void loss_kernel(const void* __restrict__ negv) {
    const int warp = threadIdx.x >> 5;
    const int lane = threadIdx.x & 31;
    const int gid  = blockIdx.x * 8 + warp;      // 0 .. 24575
    const int hi   = gid >> 13;
    const int n    = gid & (BT - 1);

    const int k = c_k[hi];
    const int L = 512 - k;
    const int NR = 16 * L;

    if (n >= NR) {
        if (lane == 0) g_row[gid] = 0.0f;
        return;
    }

    const int b = n / L;
    const int l = n - b * L;
    const int m = b * 512 + l;

    __shared__ __half sy_all[8 * DIM];           // 4 KB: per-warp f16 y
    __half* sy_h = sy_all + warp * DIM;

    // ---- phase 1: norm(y) and pos logit, fp32, warp-local ----
    const float4* yp = (const float4*)(g_pred + (long long)m * PREDN + hi * DIM);
    const float4* zp = (const float4*)(g_allz + (long long)(m + k) * DIM);
    float4 ya = yp[lane], yb = yp[lane + 32];
    float4 za = zp[lane], zb = zp[lane + 32];
    float v1 = ya.x*ya.x + ya.y*ya.y + ya.z*ya.z + ya.w*ya.w
             + yb.x*yb.x + yb.y*yb.y + yb.z*yb.z + yb.w*yb.w;
    float v2 = ya.x*za.x + ya.y*za.y + ya.z*za.z + ya.w*za.w
             + yb.x*zb.x + yb.y*zb.y + yb.z*zb.z + yb.w*zb.w;
    v1 = warp_sum(v1);
    v2 = warp_sum(v2);
    const float invn = 1.0f / fmaxf(sqrtf(v1), 1e-12f);
    const float pos  = v2 * invn * 14.285714286f;   // cos/TEMP

    // unit y in f16: lane covers elems [4*lane,4*lane+4) and [128+4*lane, ..)
    {
        __half2* sh2 = (__half2*)sy_h;
        sh2[2*lane+0]    = __floats2half2_rn(ya.x*invn, ya.y*invn);
        sh2[2*lane+1]    = __floats2half2_rn(ya.z*invn, ya.w*invn);
        sh2[64+2*lane+0] = __floats2half2_rn(yb.x*invn, yb.y*invn);
        sh2[64+2*lane+1] = __floats2half2_rn(yb.z*invn, yb.w*invn);
    }
    __syncwarp();

    // lane's fixed 32-elem y chunk: elems [32c, 32c+32)
    const int seg = lane >> 3;                   // 0..3
    const int c   = lane & 7;                    // 0..7
    const uint4* syh4 = (const uint4*)sy_h;
    uint4 t0 = syh4[4*c + 0];
    uint4 t1 = syh4[4*c + 1];
    uint4 t2 = syh4[4*c + 2];
    uint4 t3 = syh4[4*c + 3];

    const int is64 = g_is64;
    const long long base = ((long long)(hi * BT + n)) * NNEG;
    const int* neg32 = (const int*)negv;         // LE low word valid for both widths

    // ---- phase 2: 128 negatives, 4 per pass (8 lanes each) ----
    float ssum = 0.0f;
    #pragma unroll 4
    for (int pass = 0; pass < 32; ++pass) {
        int j = (pass << 2) + seg;
        long long o = base + j;
        int idx = neg32[is64 ? (o << 1) : o];
        const uint4* rowp = (const uint4*)(g_allz8 + ((size_t)idx << 8));
        uint4 u0 = rowp[2*c];                    // bytes [32c, 32c+16)
        uint4 u1 = rowp[2*c + 1];                // bytes [32c+16, 32c+32)

        __half2 acc = __float2half2_rn(0.0f);
        __half2 a0, a1;
        f8x4_to_h2(u0.x, a0, a1);
        acc = __hfma2(a0, u32_as_h2(t0.x), acc);
        acc = __hfma2(a1, u32_as_h2(t0.y), acc);
        f8x4_to_h2(u0.y, a0, a1);
        acc = __hfma2(a0, u32_as_h2(t0.z), acc);
        acc = __hfma2(a1, u32_as_h2(t0.w), acc);
        f8x4_to_h2(u0.z, a0, a1);
        acc = __hfma2(a0, u32_as_h2(t1.x), acc);
        acc = __hfma2(a1, u32_as_h2(t1.y), acc);
        f8x4_to_h2(u0.w, a0, a1);
        acc = __hfma2(a0, u32_as_h2(t1.z), acc);
        acc = __hfma2(a1, u32_as_h2(t1.w), acc);
        f8x4_to_h2(u1.x, a0, a1);
        acc = __hfma2(a0, u32_as_h2(t2.x), acc);
        acc = __hfma2(a1, u32_as_h2(t2.y), acc);
        f8x4_to_h2(u1.y, a0, a1);
        acc = __hfma2(a0, u32_as_h2(t2.z), acc);
        acc = __hfma2(a1, u32_as_h2(t2.w), acc);
        f8x4_to_h2(u1.z, a0, a1);
        acc = __hfma2(a0, u32_as_h2(t3.x), acc);
        acc = __hfma2(a1, u32_as_h2(t3.y), acc);
        f8x4_to_h2(u1.w, a0, a1);
        acc = __hfma2(a0, u32_as_h2(t3.z), acc);
        acc = __hfma2(a1, u32_as_h2(t3.w), acc);

        float d = __low2float(acc) + __high2float(acc);
        d += __shfl_xor_sync(0xffffffffu, d, 1);
        d += __shfl_xor_sync(0xffffffffu, d, 2);
        d += __shfl_xor_sync(0xffffffffu, d, 4);
        ssum += __expf(d * 14.285714286f);       // logit in [-14.5, 14.5]: safe
    }

    // combine 4 segments (values identical within a segment)
    ssum += __shfl_xor_sync(0xffffffffu, ssum, 8);
    ssum += __shfl_xor_sync(0xffffffffu, ssum, 16);

    if (lane == 0) {
        float lse = logf(ssum + expf(pos));
        g_row[gid] = c_w[hi] * (lse - pos) / (float)NR;
    }
}

// ---------------------------------------------------------------------------
// Deterministic final reduction of NH*BT per-row losses.
// ---------------------------------------------------------------------------
__global__ __launch_bounds__(256) void reduce_kernel(float* __restrict__ out) {
    __shared__ float s[256];
    float acc = 0.0f;
    for (int i = threadIdx.x; i < NH * BT; i += 256) acc += g_row[i];
    s[threadIdx.x] = acc;
    __syncthreads();
    for (int st = 128; st; st >>= 1) {
        if (threadIdx.x < st) s[threadIdx.x] += s[threadIdx.x + st];
        __syncthreads();
    }
    if (threadIdx.x == 0) out[0] = s[0];
}

// ---------------------------------------------------------------------------
extern "C" void kernel_launch(void* const* d_in, const int* in_sizes, int n_in,
                              void* d_out, int out_size) {
    const float* z_seq = (const float*)d_in[0];   // (16,512,256) f32
    const float* preds = (const float*)d_in[1];   // (3,256,256)  f32
    const void*  neg   = d_in[2];                 // (3,8192,128) int32 or int64

    detect_kernel<<<1, 1>>>((const long long*)neg);
    norm_kernel<<<BT / 8, 256>>>(z_seq);
    gemm_kernel<<<dim3(PREDN / 64, BT / 128), 256>>>(z_seq, preds);
    loss_kernel<<<NH * BT / 8, 256>>>(neg);
    reduce_kernel<<<1, 256>>>((float*)d_out);
}

// round 11
// speedup vs baseline: 3.5622x; 1.6465x over previous
#include <cuda_runtime.h>
#include <cuda_fp16.h>

#define BT    8192          // B*T
#define DIM   256
#define NH    3
#define NNEG  128
#define PREDN (NH*DIM)      // 768

__device__ float         g_allz [BT * DIM];    // normalized z table, fp32 (8 MB) — pos logits
__device__ unsigned char g_allz8[BT * DIM];    // normalized z table, e4m3 (2 MB) — neg gathers
__device__ __half        g_a16  [BT * DIM];    // raw z, fp16 (4 MB) — GEMM A operand
__device__ __half        g_w16  [PREDN * DIM]; // preds, fp16 (0.4 MB) — GEMM B operand
__device__ float         g_pred [BT * PREDN];  // z_pred for all horizons (24 MB)
__device__ float         g_row  [NH * BT];     // per-row weighted losses
__device__ int           g_is64;

__constant__ int   c_k[3] = {1, 5, 21};
__constant__ float c_w[3] = {0.6004450f, 0.26852716f, 0.13102784f}; // (1/sqrt k)/tot

// ---- helpers -------------------------------------------------------------
__device__ __forceinline__ float warp_sum(float v) {
    #pragma unroll
    for (int o = 16; o; o >>= 1) v += __shfl_xor_sync(0xffffffffu, v, o);
    return v;
}
__device__ __forceinline__ unsigned short f2_to_e4m3x2(float lo, float hi) {
    unsigned short s;
    asm("cvt.rn.satfinite.e4m3x2.f32 %0, %1, %2;" : "=h"(s) : "f"(hi), "f"(lo));
    return s;
}
__device__ __forceinline__ void f8x4_to_h2(unsigned w, __half2& a0, __half2& a1) {
    unsigned r0, r1;
    asm("{\n\t.reg .b16 lo, hi;\n\t"
        "mov.b32 {lo, hi}, %2;\n\t"
        "cvt.rn.f16x2.e4m3x2 %0, lo;\n\t"
        "cvt.rn.f16x2.e4m3x2 %1, hi;\n\t}"
        : "=r"(r0), "=r"(r1) : "r"(w));
    a0 = *reinterpret_cast<__half2*>(&r0);
    a1 = *reinterpret_cast<__half2*>(&r1);
}
__device__ __forceinline__ __half2 u32_as_h2(unsigned w) {
    return *reinterpret_cast<__half2*>(&w);
}
__device__ __forceinline__ unsigned sptr(const void* p) {
    return (unsigned)__cvta_generic_to_shared(p);
}

// ---------------------------------------------------------------------------
__global__ void detect_kernel(const long long* __restrict__ neg) {
    int ok = 1;
    for (int i = 0; i < 64; ++i) {
        unsigned long long v = (unsigned long long)neg[i];
        if (v >= (unsigned long long)BT) { ok = 0; break; }
    }
    g_is64 = ok;
}

// ---------------------------------------------------------------------------
// Normalize rows -> g_allz (fp32), g_allz8 (e4m3); raw fp16 copy -> g_a16.
// ---------------------------------------------------------------------------
__global__ __launch_bounds__(256) void norm_kernel(const float* __restrict__ z) {
    int warp = threadIdx.x >> 5;
    int lane = threadIdx.x & 31;
    int row  = blockIdx.x * 8 + warp;

    const float4* src = (const float4*)(z + (long long)row * DIM);
    float4 a = src[lane];
    float4 b = src[lane + 32];

    // raw fp16 copy (BEFORE normalization) for the GEMM A operand
    {
        __half2* a16 = (__half2*)(g_a16 + (long long)row * DIM);
        a16[2*lane+0]    = __floats2half2_rn(a.x, a.y);
        a16[2*lane+1]    = __floats2half2_rn(a.z, a.w);
        a16[64+2*lane+0] = __floats2half2_rn(b.x, b.y);
        a16[64+2*lane+1] = __floats2half2_rn(b.z, b.w);
    }

    float s = a.x*a.x + a.y*a.y + a.z*a.z + a.w*a.w
            + b.x*b.x + b.y*b.y + b.z*b.z + b.w*b.w;
    s = warp_sum(s);
    float inv = 1.0f / fmaxf(sqrtf(s), 1e-12f);

    a.x *= inv; a.y *= inv; a.z *= inv; a.w *= inv;
    b.x *= inv; b.y *= inv; b.z *= inv; b.w *= inv;

    float4* dst = (float4*)(g_allz + (long long)row * DIM);
    dst[lane]      = a;
    dst[lane + 32] = b;

    unsigned* r8 = (unsigned*)(g_allz8 + (long long)row * DIM);
    unsigned w0 = (unsigned)f2_to_e4m3x2(a.x, a.y) | ((unsigned)f2_to_e4m3x2(a.z, a.w) << 16);
    unsigned w1 = (unsigned)f2_to_e4m3x2(b.x, b.y) | ((unsigned)f2_to_e4m3x2(b.z, b.w) << 16);
    r8[lane]      = w0;
    r8[32 + lane] = w1;
}

// ---------------------------------------------------------------------------
// preds f32 -> f16 (196608 elems, 4 per thread).
// ---------------------------------------------------------------------------
__global__ __launch_bounds__(256) void predconv_kernel(const float* __restrict__ w) {
    int i = blockIdx.x * 256 + threadIdx.x;          // 0 .. 49151
    float4 v = *((const float4*)w + i);
    __half2* out = (__half2*)g_w16 + 2 * i;
    out[0] = __floats2half2_rn(v.x, v.y);
    out[1] = __floats2half2_rn(v.z, v.w);
}

// ---------------------------------------------------------------------------
// HMMA GEMM: C[m][n] = sum_k A16[m][k] * W16[n][k], fp32 accumulate.
// BM=128, BN=64, BK=32; 8 warps (4x2); warp tile 32x32 = 2x4 m16n8k16.
// Smem rows padded to 40 halves (80 B) -> conflict-free ldmatrix.
// ---------------------------------------------------------------------------
__global__ __launch_bounds__(256) void gemm16_kernel(const __half* __restrict__ A16,
                                                     const __half* __restrict__ W16) {
    __shared__ __half As[128 * 40];
    __shared__ __half Bs[64 * 40];

    const int tid  = threadIdx.x;
    const int lane = tid & 31, warp = tid >> 5;
    const int bn = blockIdx.x, bm = blockIdx.y;
    const int wm = warp >> 1, wn = warp & 1;

    float c[2][4][4];
    #pragma unroll
    for (int i = 0; i < 2; ++i)
        #pragma unroll
        for (int j = 0; j < 4; ++j)
            #pragma unroll
            for (int q = 0; q < 4; ++q) c[i][j][q] = 0.0f;

    const __half* Ab = A16 + (size_t)(bm * 128) * DIM;
    const __half* Wb = W16 + (size_t)(bn * 64)  * DIM;

    // ldmatrix lane geometry
    const int a_row = wm * 32 + (lane & 15);                 // + tm*16
    const int a_col = (lane >> 4) * 8;                       // + ks
    const int b_row = wn * 32 + (lane & 7) + ((lane >> 4) << 3);  // + g*16
    const int b_col = ((lane >> 3) & 1) * 8;                 // + ks

    for (int k0 = 0; k0 < DIM; k0 += 32) {
        __syncthreads();
        #pragma unroll
        for (int r = 0; r < 2; ++r) {
            int u   = tid + r * 256;       // 512 chunks of 16B
            int row = u >> 2, q = u & 3;
            *(uint4*)(As + row * 40 + q * 8) = *(const uint4*)(Ab + row * DIM + k0 + q * 8);
        }
        {
            int row = tid >> 2, q = tid & 3;   // 256 chunks
            *(uint4*)(Bs + row * 40 + q * 8) = *(const uint4*)(Wb + row * DIM + k0 + q * 8);
        }
        __syncthreads();

        #pragma unroll
        for (int ks = 0; ks < 32; ks += 16) {
            unsigned a[2][4], bfr[2][4];
            #pragma unroll
            for (int tm = 0; tm < 2; ++tm) {
                unsigned addr = sptr(As + (a_row + tm * 16) * 40 + a_col + ks);
                asm volatile("ldmatrix.sync.aligned.m8n8.x4.shared.b16 {%0,%1,%2,%3},[%4];"
                    : "=r"(a[tm][0]), "=r"(a[tm][1]), "=r"(a[tm][2]), "=r"(a[tm][3])
                    : "r"(addr));
            }
            #pragma unroll
            for (int g = 0; g < 2; ++g) {
                unsigned addr = sptr(Bs + (b_row + g * 16) * 40 + b_col + ks);
                asm volatile("ldmatrix.sync.aligned.m8n8.x4.shared.b16 {%0,%1,%2,%3},[%4];"
                    : "=r"(bfr[g][0]), "=r"(bfr[g][1]), "=r"(bfr[g][2]), "=r"(bfr[g][3])
                    : "r"(addr));
            }
            #pragma unroll
            for (int tm = 0; tm < 2; ++tm)
                #pragma unroll
                for (int tn = 0; tn < 4; ++tn) {
                    unsigned b0 = bfr[tn >> 1][(tn & 1) * 2 + 0];
                    unsigned b1 = bfr[tn >> 1][(tn & 1) * 2 + 1];
                    asm volatile(
                        "mma.sync.aligned.m16n8k16.row.col.f32.f16.f16.f32 "
                        "{%0,%1,%2,%3},{%4,%5,%6,%7},{%8,%9},{%0,%1,%2,%3};"
                        : "+f"(c[tm][tn][0]), "+f"(c[tm][tn][1]),
                          "+f"(c[tm][tn][2]), "+f"(c[tm][tn][3])
                        : "r"(a[tm][0]), "r"(a[tm][1]), "r"(a[tm][2]), "r"(a[tm][3]),
                          "r"(b0), "r"(b1));
                }
        }
    }

    // store: c0,c1 -> (row, col..col+1); c2,c3 -> (row+8, ...)
    const int cm = lane >> 2, cn2 = (lane & 3) * 2;
    #pragma unroll
    for (int tm = 0; tm < 2; ++tm)
        #pragma unroll
        for (int tn = 0; tn < 4; ++tn) {
            int row0 = bm * 128 + wm * 32 + tm * 16 + cm;
            int col  = bn * 64 + wn * 32 + tn * 8 + cn2;
            float* p0 = g_pred + (size_t)row0 * PREDN + col;
            *(float2*)p0 = make_float2(c[tm][tn][0], c[tm][tn][1]);
            *(float2*)(p0 + 8 * PREDN) = make_float2(c[tm][tn][2], c[tm][tn][3]);
        }
}

// ---------------------------------------------------------------------------
// Loss: ONE WARP PER ROW — no block barriers (unchanged from R10 win).
// ---------------------------------------------------------------------------
__global__ __launch_bounds__(256, 5) void loss_kernel(const void* __restrict__ negv) {
    const int warp = threadIdx.x >> 5;
    const int lane = threadIdx.x & 31;
    const int gid  = blockIdx.x * 8 + warp;
    const int hi   = gid >> 13;
    const int n    = gid & (BT - 1);

    const int k = c_k[hi];
    const int L = 512 - k;
    const int NR = 16 * L;

    if (n >= NR) {
        if (lane == 0) g_row[gid] = 0.0f;
        return;
    }

    const int b = n / L;
    const int l = n - b * L;
    const int m = b * 512 + l;

    __shared__ __half sy_all[8 * DIM];
    __half* sy_h = sy_all + warp * DIM;

    const float4* yp = (const float4*)(g_pred + (long long)m * PREDN + hi * DIM);
    const float4* zp = (const float4*)(g_allz + (long long)(m + k) * DIM);
    float4 ya = yp[lane], yb = yp[lane + 32];
    float4 za = zp[lane], zb = zp[lane + 32];
    float v1 = ya.x*ya.x + ya.y*ya.y + ya.z*ya.z + ya.w*ya.w
             + yb.x*yb.x + yb.y*yb.y + yb.z*yb.z + yb.w*yb.w;
    float v2 = ya.x*za.x + ya.y*za.y + ya.z*za.z + ya.w*za.w
             + yb.x*zb.x + yb.y*zb.y + yb.z*zb.z + yb.w*zb.w;
    v1 = warp_sum(v1);
    v2 = warp_sum(v2);
    const float invn = 1.0f / fmaxf(sqrtf(v1), 1e-12f);
    const float pos  = v2 * invn * 14.285714286f;

    {
        __half2* sh2 = (__half2*)sy_h;
        sh2[2*lane+0]    = __floats2half2_rn(ya.x*invn, ya.y*invn);
        sh2[2*lane+1]    = __floats2half2_rn(ya.z*invn, ya.w*invn);
        sh2[64+2*lane+0] = __floats2half2_rn(yb.x*invn, yb.y*invn);
        sh2[64+2*lane+1] = __floats2half2_rn(yb.z*invn, yb.w*invn);
    }
    __syncwarp();

    const int seg = lane >> 3;
    const int c   = lane & 7;
    const uint4* syh4 = (const uint4*)sy_h;
    uint4 t0 = syh4[4*c + 0];
    uint4 t1 = syh4[4*c + 1];
    uint4 t2 = syh4[4*c + 2];
    uint4 t3 = syh4[4*c + 3];

    const int is64 = g_is64;
    const long long base = ((long long)(hi * BT + n)) * NNEG;
    const int* neg32 = (const int*)negv;

    float ssum = 0.0f;
    #pragma unroll 4
    for (int pass = 0; pass < 32; ++pass) {
        int j = (pass << 2) + seg;
        long long o = base + j;
        int idx = neg32[is64 ? (o << 1) : o];
        const uint4* rowp = (const uint4*)(g_allz8 + ((size_t)idx << 8));
        uint4 u0 = rowp[2*c];
        uint4 u1 = rowp[2*c + 1];

        __half2 acc = __float2half2_rn(0.0f);
        __half2 a0, a1;
        f8x4_to_h2(u0.x, a0, a1);
        acc = __hfma2(a0, u32_as_h2(t0.x), acc);
        acc = __hfma2(a1, u32_as_h2(t0.y), acc);
        f8x4_to_h2(u0.y, a0, a1);
        acc = __hfma2(a0, u32_as_h2(t0.z), acc);
        acc = __hfma2(a1, u32_as_h2(t0.w), acc);
        f8x4_to_h2(u0.z, a0, a1);
        acc = __hfma2(a0, u32_as_h2(t1.x), acc);
        acc = __hfma2(a1, u32_as_h2(t1.y), acc);
        f8x4_to_h2(u0.w, a0, a1);
        acc = __hfma2(a0, u32_as_h2(t1.z), acc);
        acc = __hfma2(a1, u32_as_h2(t1.w), acc);
        f8x4_to_h2(u1.x, a0, a1);
        acc = __hfma2(a0, u32_as_h2(t2.x), acc);
        acc = __hfma2(a1, u32_as_h2(t2.y), acc);
        f8x4_to_h2(u1.y, a0, a1);
        acc = __hfma2(a0, u32_as_h2(t2.z), acc);
        acc = __hfma2(a1, u32_as_h2(t2.w), acc);
        f8x4_to_h2(u1.z, a0, a1);
        acc = __hfma2(a0, u32_as_h2(t3.x), acc);
        acc = __hfma2(a1, u32_as_h2(t3.y), acc);
        f8x4_to_h2(u1.w, a0, a1);
        acc = __hfma2(a0, u32_as_h2(t3.z), acc);
        acc = __hfma2(a1, u32_as_h2(t3.w), acc);

        float d = __low2float(acc) + __high2float(acc);
        d += __shfl_xor_sync(0xffffffffu, d, 1);
        d += __shfl_xor_sync(0xffffffffu, d, 2);
        d += __shfl_xor_sync(0xffffffffu, d, 4);
        ssum += __expf(d * 14.285714286f);
    }

    ssum += __shfl_xor_sync(0xffffffffu, ssum, 8);
    ssum += __shfl_xor_sync(0xffffffffu, ssum, 16);

    if (lane == 0) {
        float lse = logf(ssum + expf(pos));
        g_row[gid] = c_w[hi] * (lse - pos) / (float)NR;
    }
}

// ---------------------------------------------------------------------------
__global__ __launch_bounds__(256) void reduce_kernel(float* __restrict__ out) {
    __shared__ float s[256];
    float acc = 0.0f;
    for (int i = threadIdx.x; i < NH * BT; i += 256) acc += g_row[i];
    s[threadIdx.x] = acc;
    __syncthreads();
    for (int st = 128; st; st >>= 1) {
        if (threadIdx.x < st) s[threadIdx.x] += s[threadIdx.x + st];
        __syncthreads();
    }
    if (threadIdx.x == 0) out[0] = s[0];
}

// ---------------------------------------------------------------------------
extern "C" void kernel_launch(void* const* d_in, const int* in_sizes, int n_in,
                              void* d_out, int out_size) {
    const float* z_seq = (const float*)d_in[0];   // (16,512,256) f32
    const float* preds = (const float*)d_in[1];   // (3,256,256)  f32
    const void*  neg   = d_in[2];                 // (3,8192,128) int32 or int64

    __half* a16 = nullptr;  __half* w16 = nullptr;
    cudaGetSymbolAddress((void**)&a16, g_a16);
    cudaGetSymbolAddress((void**)&w16, g_w16);

    detect_kernel<<<1, 1>>>((const long long*)neg);
    norm_kernel<<<BT / 8, 256>>>(z_seq);
    predconv_kernel<<<PREDN * DIM / 4 / 256, 256>>>(preds);
    gemm16_kernel<<<dim3(PREDN / 64, BT / 128), 256>>>(a16, w16);
    loss_kernel<<<NH * BT / 8, 256>>>(neg);
    reduce_kernel<<<1, 256>>>((float*)d_out);
}

// round 12
// speedup vs baseline: 3.5633x; 1.0003x over previous
#include <cuda_runtime.h>
#include <cuda_fp16.h>

#define BT    8192          // B*T
#define DIM   256
#define NH    3
#define NNEG  128
#define PREDN (NH*DIM)      // 768

__device__ float         g_allz [BT * DIM];    // normalized z table, fp32 (8 MB) — pos logits
__device__ unsigned char g_allz8[BT * DIM];    // normalized z table, e4m3 (2 MB) — neg gathers
__device__ __half        g_a16  [BT * DIM];    // raw z, fp16 (4 MB) — GEMM A operand
__device__ __half        g_w16  [PREDN * DIM]; // preds, fp16 (0.4 MB) — GEMM B operand
__device__ float         g_pred [BT * PREDN];  // z_pred for all horizons (24 MB)
__device__ float         g_row  [NH * BT];     // per-row weighted losses
__device__ int           g_is64;

__constant__ int   c_k[3] = {1, 5, 21};
__constant__ float c_w[3] = {0.6004450f, 0.26852716f, 0.13102784f}; // (1/sqrt k)/tot

// ---- helpers -------------------------------------------------------------
__device__ __forceinline__ float warp_sum(float v) {
    #pragma unroll
    for (int o = 16; o; o >>= 1) v += __shfl_xor_sync(0xffffffffu, v, o);
    return v;
}
__device__ __forceinline__ unsigned short f2_to_e4m3x2(float lo, float hi) {
    unsigned short s;
    asm("cvt.rn.satfinite.e4m3x2.f32 %0, %1, %2;" : "=h"(s) : "f"(hi), "f"(lo));
    return s;
}
__device__ __forceinline__ void f8x4_to_h2(unsigned w, __half2& a0, __half2& a1) {
    unsigned r0, r1;
    asm("{\n\t.reg .b16 lo, hi;\n\t"
        "mov.b32 {lo, hi}, %2;\n\t"
        "cvt.rn.f16x2.e4m3x2 %0, lo;\n\t"
        "cvt.rn.f16x2.e4m3x2 %1, hi;\n\t}"
        : "=r"(r0), "=r"(r1) : "r"(w));
    a0 = *reinterpret_cast<__half2*>(&r0);
    a1 = *reinterpret_cast<__half2*>(&r1);
}
__device__ __forceinline__ __half2 u32_as_h2(unsigned w) {
    return *reinterpret_cast<__half2*>(&w);
}
__device__ __forceinline__ unsigned sptr(const void* p) {
    return (unsigned)__cvta_generic_to_shared(p);
}

// ---------------------------------------------------------------------------
__global__ void detect_kernel(const long long* __restrict__ neg) {
    int ok = 1;
    for (int i = 0; i < 64; ++i) {
        unsigned long long v = (unsigned long long)neg[i];
        if (v >= (unsigned long long)BT) { ok = 0; break; }
    }
    g_is64 = ok;
}

// ---------------------------------------------------------------------------
// Normalize rows -> g_allz (fp32), g_allz8 (e4m3); raw fp16 copy -> g_a16.
// ---------------------------------------------------------------------------
__global__ __launch_bounds__(256) void norm_kernel(const float* __restrict__ z) {
    int warp = threadIdx.x >> 5;
    int lane = threadIdx.x & 31;
    int row  = blockIdx.x * 8 + warp;

    const float4* src = (const float4*)(z + (long long)row * DIM);
    float4 a = src[lane];
    float4 b = src[lane + 32];

    // raw fp16 copy (BEFORE normalization) for the GEMM A operand
    {
        __half2* a16 = (__half2*)(g_a16 + (long long)row * DIM);
        a16[2*lane+0]    = __floats2half2_rn(a.x, a.y);
        a16[2*lane+1]    = __floats2half2_rn(a.z, a.w);
        a16[64+2*lane+0] = __floats2half2_rn(b.x, b.y);
        a16[64+2*lane+1] = __floats2half2_rn(b.z, b.w);
    }

    float s = a.x*a.x + a.y*a.y + a.z*a.z + a.w*a.w
            + b.x*b.x + b.y*b.y + b.z*b.z + b.w*b.w;
    s = warp_sum(s);
    float inv = 1.0f / fmaxf(sqrtf(s), 1e-12f);

    a.x *= inv; a.y *= inv; a.z *= inv; a.w *= inv;
    b.x *= inv; b.y *= inv; b.z *= inv; b.w *= inv;

    float4* dst = (float4*)(g_allz + (long long)row * DIM);
    dst[lane]      = a;
    dst[lane + 32] = b;

    unsigned* r8 = (unsigned*)(g_allz8 + (long long)row * DIM);
    unsigned w0 = (unsigned)f2_to_e4m3x2(a.x, a.y) | ((unsigned)f2_to_e4m3x2(a.z, a.w) << 16);
    unsigned w1 = (unsigned)f2_to_e4m3x2(b.x, b.y) | ((unsigned)f2_to_e4m3x2(b.z, b.w) << 16);
    r8[lane]      = w0;
    r8[32 + lane] = w1;
}

// ---------------------------------------------------------------------------
// preds f32 -> f16 (196608 elems, 4 per thread).
// ---------------------------------------------------------------------------
__global__ __launch_bounds__(256) void predconv_kernel(const float* __restrict__ w) {
    int i = blockIdx.x * 256 + threadIdx.x;          // 0 .. 49151
    float4 v = *((const float4*)w + i);
    __half2* out = (__half2*)g_w16 + 2 * i;
    out[0] = __floats2half2_rn(v.x, v.y);
    out[1] = __floats2half2_rn(v.z, v.w);
}

// ---------------------------------------------------------------------------
// HMMA GEMM: C[m][n] = sum_k A16[m][k] * W16[n][k], fp32 accumulate.
// BM=128, BN=64, BK=32; 8 warps (4x2); warp tile 32x32 = 2x4 m16n8k16.
// Smem rows padded to 40 halves (80 B) -> conflict-free ldmatrix.
// ---------------------------------------------------------------------------
__global__ __launch_bounds__(256) void gemm16_kernel(const __half* __restrict__ A16,
                                                     const __half* __restrict__ W16) {
    __shared__ __half As[128 * 40];
    __shared__ __half Bs[64 * 40];

    const int tid  = threadIdx.x;
    const int lane = tid & 31, warp = tid >> 5;
    const int bn = blockIdx.x, bm = blockIdx.y;
    const int wm = warp >> 1, wn = warp & 1;

    float c[2][4][4];
    #pragma unroll
    for (int i = 0; i < 2; ++i)
        #pragma unroll
        for (int j = 0; j < 4; ++j)
            #pragma unroll
            for (int q = 0; q < 4; ++q) c[i][j][q] = 0.0f;

    const __half* Ab = A16 + (size_t)(bm * 128) * DIM;
    const __half* Wb = W16 + (size_t)(bn * 64)  * DIM;

    // ldmatrix lane geometry
    const int a_row = wm * 32 + (lane & 15);                 // + tm*16
    const int a_col = (lane >> 4) * 8;                       // + ks
    const int b_row = wn * 32 + (lane & 7) + ((lane >> 4) << 3);  // + g*16
    const int b_col = ((lane >> 3) & 1) * 8;                 // + ks

    for (int k0 = 0; k0 < DIM; k0 += 32) {
        __syncthreads();
        #pragma unroll
        for (int r = 0; r < 2; ++r) {
            int u   = tid + r * 256;       // 512 chunks of 16B
            int row = u >> 2, q = u & 3;
            *(uint4*)(As + row * 40 + q * 8) = *(const uint4*)(Ab + row * DIM + k0 + q * 8);
        }
        {
            int row = tid >> 2, q = tid & 3;   // 256 chunks
            *(uint4*)(Bs + row * 40 + q * 8) = *(const uint4*)(Wb + row * DIM + k0 + q * 8);
        }
        __syncthreads();

        #pragma unroll
        for (int ks = 0; ks < 32; ks += 16) {
            unsigned a[2][4], bfr[2][4];
            #pragma unroll
            for (int tm = 0; tm < 2; ++tm) {
                unsigned addr = sptr(As + (a_row + tm * 16) * 40 + a_col + ks);
                asm volatile("ldmatrix.sync.aligned.m8n8.x4.shared.b16 {%0,%1,%2,%3},[%4];"
                    : "=r"(a[tm][0]), "=r"(a[tm][1]), "=r"(a[tm][2]), "=r"(a[tm][3])
                    : "r"(addr));
            }
            #pragma unroll
            for (int g = 0; g < 2; ++g) {
                unsigned addr = sptr(Bs + (b_row + g * 16) * 40 + b_col + ks);
                asm volatile("ldmatrix.sync.aligned.m8n8.x4.shared.b16 {%0,%1,%2,%3},[%4];"
                    : "=r"(bfr[g][0]), "=r"(bfr[g][1]), "=r"(bfr[g][2]), "=r"(bfr[g][3])
                    : "r"(addr));
            }
            #pragma unroll
            for (int tm = 0; tm < 2; ++tm)
                #pragma unroll
                for (int tn = 0; tn < 4; ++tn) {
                    unsigned b0 = bfr[tn >> 1][(tn & 1) * 2 + 0];
                    unsigned b1 = bfr[tn >> 1][(tn & 1) * 2 + 1];
                    asm volatile(
                        "mma.sync.aligned.m16n8k16.row.col.f32.f16.f16.f32 "
                        "{%0,%1,%2,%3},{%4,%5,%6,%7},{%8,%9},{%0,%1,%2,%3};"
                        : "+f"(c[tm][tn][0]), "+f"(c[tm][tn][1]),
                          "+f"(c[tm][tn][2]), "+f"(c[tm][tn][3])
                        : "r"(a[tm][0]), "r"(a[tm][1]), "r"(a[tm][2]), "r"(a[tm][3]),
                          "r"(b0), "r"(b1));
                }
        }
    }

    // store: c0,c1 -> (row, col..col+1); c2,c3 -> (row+8, ...)
    const int cm = lane >> 2, cn2 = (lane & 3) * 2;
    #pragma unroll
    for (int tm = 0; tm < 2; ++tm)
        #pragma unroll
        for (int tn = 0; tn < 4; ++tn) {
            int row0 = bm * 128 + wm * 32 + tm * 16 + cm;
            int col  = bn * 64 + wn * 32 + tn * 8 + cn2;
            float* p0 = g_pred + (size_t)row0 * PREDN + col;
            *(float2*)p0 = make_float2(c[tm][tn][0], c[tm][tn][1]);
            *(float2*)(p0 + 8 * PREDN) = make_float2(c[tm][tn][2], c[tm][tn][3]);
        }
}

// ---------------------------------------------------------------------------
// Loss: ONE WARP PER ROW — no block barriers (unchanged from R10 win).
// ---------------------------------------------------------------------------
__global__ __launch_bounds__(256, 5) void loss_kernel(const void* __restrict__ negv) {
    const int warp = threadIdx.x >> 5;
    const int lane = threadIdx.x & 31;
    const int gid  = blockIdx.x * 8 + warp;
    const int hi   = gid >> 13;
    const int n    = gid & (BT - 1);

    const int k = c_k[hi];
    const int L = 512 - k;
    const int NR = 16 * L;

    if (n >= NR) {
        if (lane == 0) g_row[gid] = 0.0f;
        return;
    }

    const int b = n / L;
    const int l = n - b * L;
    const int m = b * 512 + l;

    __shared__ __half sy_all[8 * DIM];
    __half* sy_h = sy_all + warp * DIM;

    const float4* yp = (const float4*)(g_pred + (long long)m * PREDN + hi * DIM);
    const float4* zp = (const float4*)(g_allz + (long long)(m + k) * DIM);
    float4 ya = yp[lane], yb = yp[lane + 32];
    float4 za = zp[lane], zb = zp[lane + 32];
    float v1 = ya.x*ya.x + ya.y*ya.y + ya.z*ya.z + ya.w*ya.w
             + yb.x*yb.x + yb.y*yb.y + yb.z*yb.z + yb.w*yb.w;
    float v2 = ya.x*za.x + ya.y*za.y + ya.z*za.z + ya.w*za.w
             + yb.x*zb.x + yb.y*zb.y + yb.z*zb.z + yb.w*zb.w;
    v1 = warp_sum(v1);
    v2 = warp_sum(v2);
    const float invn = 1.0f / fmaxf(sqrtf(v1), 1e-12f);
    const float pos  = v2 * invn * 14.285714286f;

    {
        __half2* sh2 = (__half2*)sy_h;
        sh2[2*lane+0]    = __floats2half2_rn(ya.x*invn, ya.y*invn);
        sh2[2*lane+1]    = __floats2half2_rn(ya.z*invn, ya.w*invn);
        sh2[64+2*lane+0] = __floats2half2_rn(yb.x*invn, yb.y*invn);
        sh2[64+2*lane+1] = __floats2half2_rn(yb.z*invn, yb.w*invn);
    }
    __syncwarp();

    const int seg = lane >> 3;
    const int c   = lane & 7;
    const uint4* syh4 = (const uint4*)sy_h;
    uint4 t0 = syh4[4*c + 0];
    uint4 t1 = syh4[4*c + 1];
    uint4 t2 = syh4[4*c + 2];
    uint4 t3 = syh4[4*c + 3];

    const int is64 = g_is64;
    const long long base = ((long long)(hi * BT + n)) * NNEG;
    const int* neg32 = (const int*)negv;

    float ssum = 0.0f;
    #pragma unroll 4
    for (int pass = 0; pass < 32; ++pass) {
        int j = (pass << 2) + seg;
        long long o = base + j;
        int idx = neg32[is64 ? (o << 1) : o];
        const uint4* rowp = (const uint4*)(g_allz8 + ((size_t)idx << 8));
        uint4 u0 = rowp[2*c];
        uint4 u1 = rowp[2*c + 1];

        __half2 acc = __float2half2_rn(0.0f);
        __half2 a0, a1;
        f8x4_to_h2(u0.x, a0, a1);
        acc = __hfma2(a0, u32_as_h2(t0.x), acc);
        acc = __hfma2(a1, u32_as_h2(t0.y), acc);
        f8x4_to_h2(u0.y, a0, a1);
        acc = __hfma2(a0, u32_as_h2(t0.z), acc);
        acc = __hfma2(a1, u32_as_h2(t0.w), acc);
        f8x4_to_h2(u0.z, a0, a1);
        acc = __hfma2(a0, u32_as_h2(t1.x), acc);
        acc = __hfma2(a1, u32_as_h2(t1.y), acc);
        f8x4_to_h2(u0.w, a0, a1);
        acc = __hfma2(a0, u32_as_h2(t1.z), acc);
        acc = __hfma2(a1, u32_as_h2(t1.w), acc);
        f8x4_to_h2(u1.x, a0, a1);
        acc = __hfma2(a0, u32_as_h2(t2.x), acc);
        acc = __hfma2(a1, u32_as_h2(t2.y), acc);
        f8x4_to_h2(u1.y, a0, a1);
        acc = __hfma2(a0, u32_as_h2(t2.z), acc);
        acc = __hfma2(a1, u32_as_h2(t2.w), acc);
        f8x4_to_h2(u1.z, a0, a1);
        acc = __hfma2(a0, u32_as_h2(t3.x), acc);
        acc = __hfma2(a1, u32_as_h2(t3.y), acc);
        f8x4_to_h2(u1.w, a0, a1);
        acc = __hfma2(a0, u32_as_h2(t3.z), acc);
        acc = __hfma2(a1, u32_as_h2(t3.w), acc);

        float d = __low2float(acc) + __high2float(acc);
        d += __shfl_xor_sync(0xffffffffu, d, 1);
        d += __shfl_xor_sync(0xffffffffu, d, 2);
        d += __shfl_xor_sync(0xffffffffu, d, 4);
        ssum += __expf(d * 14.285714286f);
    }

    ssum += __shfl_xor_sync(0xffffffffu, ssum, 8);
    ssum += __shfl_xor_sync(0xffffffffu, ssum, 16);

    if (lane == 0) {
        float lse = logf(ssum + expf(pos));
        g_row[gid] = c_w[hi] * (lse - pos) / (float)NR;
    }
}

// ---------------------------------------------------------------------------
__global__ __launch_bounds__(256) void reduce_kernel(float* __restrict__ out) {
    __shared__ float s[256];
    float acc = 0.0f;
    for (int i = threadIdx.x; i < NH * BT; i += 256) acc += g_row[i];
    s[threadIdx.x] = acc;
    __syncthreads();
    for (int st = 128; st; st >>= 1) {
        if (threadIdx.x < st) s[threadIdx.x] += s[threadIdx.x + st];
        __syncthreads();
    }
    if (threadIdx.x == 0) out[0] = s[0];
}

// ---------------------------------------------------------------------------
extern "C" void kernel_launch(void* const* d_in, const int* in_sizes, int n_in,
                              void* d_out, int out_size) {
    const float* z_seq = (const float*)d_in[0];   // (16,512,256) f32
    const float* preds = (const float*)d_in[1];   // (3,256,256)  f32
    const void*  neg   = d_in[2];                 // (3,8192,128) int32 or int64

    __half* a16 = nullptr;  __half* w16 = nullptr;
    cudaGetSymbolAddress((void**)&a16, g_a16);
    cudaGetSymbolAddress((void**)&w16, g_w16);

    detect_kernel<<<1, 1>>>((const long long*)neg);
    norm_kernel<<<BT / 8, 256>>>(z_seq);
    predconv_kernel<<<PREDN * DIM / 4 / 256, 256>>>(preds);
    gemm16_kernel<<<dim3(PREDN / 64, BT / 128), 256>>>(a16, w16);
    loss_kernel<<<NH * BT / 8, 256>>>(neg);
    reduce_kernel<<<1, 256>>>((float*)d_out);
}

// round 14
// speedup vs baseline: 4.5121x; 1.2663x over previous
#include <cuda_runtime.h>
#include <cuda_fp16.h>

#define BT    8192          // B*T
#define DIM   256
#define NH    3
#define NNEG  128
#define PREDN (NH*DIM)      // 768

__device__ float         g_allz [BT * DIM];    // normalized z table, fp32 (8 MB) — pos logits
__device__ unsigned      g_allzq[BT * DIM / 4];// normalized z table, int8x4 (2 MB) — neg gathers
__device__ __half        g_a16  [BT * DIM];    // raw z, fp16 (4 MB) — GEMM A operand
__device__ __half        g_w16  [PREDN * DIM]; // preds, fp16 (0.4 MB) — GEMM B operand
__device__ float         g_pred [BT * PREDN];  // z_pred for all horizons (24 MB)
__device__ float         g_row  [NH * BT];     // per-row weighted losses
__device__ int           g_is64;

__constant__ int   c_k[3] = {1, 5, 21};
__constant__ float c_w[3] = {0.6004450f, 0.26852716f, 0.13102784f}; // (1/sqrt k)/tot

// logit = dot_int * (1/(127*127)) * (1/0.07)
#define LSCALE 8.857410e-4f

// ---- helpers -------------------------------------------------------------
__device__ __forceinline__ float warp_sum(float v) {
    #pragma unroll
    for (int o = 16; o; o >>= 1) v += __shfl_xor_sync(0xffffffffu, v, o);
    return v;
}
// signed dp4a on u32-typed words (data is s8x4)
__device__ __forceinline__ int dp4a_s(unsigned a, unsigned b, int c) {
    return __dp4a((int)a, (int)b, c);
}
// 4 floats (|v|<=1) -> packed s8x4, scale 127
__device__ __forceinline__ unsigned pack_s8x4(float a, float b, float c, float d) {
    int qa = __float2int_rn(a * 127.0f);
    int qb = __float2int_rn(b * 127.0f);
    int qc = __float2int_rn(c * 127.0f);
    int qd = __float2int_rn(d * 127.0f);
    return (qa & 0xff) | ((qb & 0xff) << 8) | ((qc & 0xff) << 16) | ((qd & 0xff) << 24);
}
__device__ __forceinline__ unsigned sptr(const void* p) {
    return (unsigned)__cvta_generic_to_shared(p);
}

// ---------------------------------------------------------------------------
__global__ void detect_kernel(const long long* __restrict__ neg) {
    int ok = 1;
    for (int i = 0; i < 64; ++i) {
        unsigned long long v = (unsigned long long)neg[i];
        if (v >= (unsigned long long)BT) { ok = 0; break; }
    }
    g_is64 = ok;
}

// ---------------------------------------------------------------------------
// Normalize rows -> g_allz (fp32), g_allzq (int8); raw fp16 copy -> g_a16.
// ---------------------------------------------------------------------------
__global__ __launch_bounds__(256) void norm_kernel(const float* __restrict__ z) {
    int warp = threadIdx.x >> 5;
    int lane = threadIdx.x & 31;
    int row  = blockIdx.x * 8 + warp;

    const float4* src = (const float4*)(z + (long long)row * DIM);
    float4 a = src[lane];
    float4 b = src[lane + 32];

    // raw fp16 copy (BEFORE normalization) for the GEMM A operand
    {
        __half2* a16 = (__half2*)(g_a16 + (long long)row * DIM);
        a16[2*lane+0]    = __floats2half2_rn(a.x, a.y);
        a16[2*lane+1]    = __floats2half2_rn(a.z, a.w);
        a16[64+2*lane+0] = __floats2half2_rn(b.x, b.y);
        a16[64+2*lane+1] = __floats2half2_rn(b.z, b.w);
    }

    float s = a.x*a.x + a.y*a.y + a.z*a.z + a.w*a.w
            + b.x*b.x + b.y*b.y + b.z*b.z + b.w*b.w;
    s = warp_sum(s);
    float inv = 1.0f / fmaxf(sqrtf(s), 1e-12f);

    a.x *= inv; a.y *= inv; a.z *= inv; a.w *= inv;
    b.x *= inv; b.y *= inv; b.z *= inv; b.w *= inv;

    float4* dst = (float4*)(g_allz + (long long)row * DIM);
    dst[lane]      = a;
    dst[lane + 32] = b;

    // int8 copy: word w holds elems [4w, 4w+4)
    unsigned* rq = g_allzq + (long long)row * (DIM / 4);
    rq[lane]      = pack_s8x4(a.x, a.y, a.z, a.w);    // elems 4*lane ..
    rq[32 + lane] = pack_s8x4(b.x, b.y, b.z, b.w);    // elems 128+4*lane ..
}

// ---------------------------------------------------------------------------
// preds f32 -> f16 (196608 elems, 4 per thread).
// ---------------------------------------------------------------------------
__global__ __launch_bounds__(256) void predconv_kernel(const float* __restrict__ w) {
    int i = blockIdx.x * 256 + threadIdx.x;          // 0 .. 49151
    float4 v = *((const float4*)w + i);
    __half2* out = (__half2*)g_w16 + 2 * i;
    out[0] = __floats2half2_rn(v.x, v.y);
    out[1] = __floats2half2_rn(v.z, v.w);
}

// ---------------------------------------------------------------------------
// HMMA GEMM: C[m][n] = sum_k A16[m][k] * W16[n][k], fp32 accumulate.
// BM=128, BN=64, BK=32; 8 warps (4x2); warp tile 32x32 = 2x4 m16n8k16.
// ---------------------------------------------------------------------------
__global__ __launch_bounds__(256) void gemm16_kernel(const __half* __restrict__ A16,
                                                     const __half* __restrict__ W16) {
    __shared__ __half As[128 * 40];
    __shared__ __half Bs[64 * 40];

    const int tid  = threadIdx.x;
    const int lane = tid & 31, warp = tid >> 5;
    const int bn = blockIdx.x, bm = blockIdx.y;
    const int wm = warp >> 1, wn = warp & 1;

    float c[2][4][4];
    #pragma unroll
    for (int i = 0; i < 2; ++i)
        #pragma unroll
        for (int j = 0; j < 4; ++j)
            #pragma unroll
            for (int q = 0; q < 4; ++q) c[i][j][q] = 0.0f;

    const __half* Ab = A16 + (size_t)(bm * 128) * DIM;
    const __half* Wb = W16 + (size_t)(bn * 64)  * DIM;

    const int a_row = wm * 32 + (lane & 15);
    const int a_col = (lane >> 4) * 8;
    const int b_row = wn * 32 + (lane & 7) + ((lane >> 4) << 3);
    const int b_col = ((lane >> 3) & 1) * 8;

    for (int k0 = 0; k0 < DIM; k0 += 32) {
        __syncthreads();
        #pragma unroll
        for (int r = 0; r < 2; ++r) {
            int u   = tid + r * 256;
            int row = u >> 2, q = u & 3;
            *(uint4*)(As + row * 40 + q * 8) = *(const uint4*)(Ab + row * DIM + k0 + q * 8);
        }
        {
            int row = tid >> 2, q = tid & 3;
            *(uint4*)(Bs + row * 40 + q * 8) = *(const uint4*)(Wb + row * DIM + k0 + q * 8);
        }
        __syncthreads();

        #pragma unroll
        for (int ks = 0; ks < 32; ks += 16) {
            unsigned a[2][4], bfr[2][4];
            #pragma unroll
            for (int tm = 0; tm < 2; ++tm) {
                unsigned addr = sptr(As + (a_row + tm * 16) * 40 + a_col + ks);
                asm volatile("ldmatrix.sync.aligned.m8n8.x4.shared.b16 {%0,%1,%2,%3},[%4];"
                    : "=r"(a[tm][0]), "=r"(a[tm][1]), "=r"(a[tm][2]), "=r"(a[tm][3])
                    : "r"(addr));
            }
            #pragma unroll
            for (int g = 0; g < 2; ++g) {
                unsigned addr = sptr(Bs + (b_row + g * 16) * 40 + b_col + ks);
                asm volatile("ldmatrix.sync.aligned.m8n8.x4.shared.b16 {%0,%1,%2,%3},[%4];"
                    : "=r"(bfr[g][0]), "=r"(bfr[g][1]), "=r"(bfr[g][2]), "=r"(bfr[g][3])
                    : "r"(addr));
            }
            #pragma unroll
            for (int tm = 0; tm < 2; ++tm)
                #pragma unroll
                for (int tn = 0; tn < 4; ++tn) {
                    unsigned b0 = bfr[tn >> 1][(tn & 1) * 2 + 0];
                    unsigned b1 = bfr[tn >> 1][(tn & 1) * 2 + 1];
                    asm volatile(
                        "mma.sync.aligned.m16n8k16.row.col.f32.f16.f16.f32 "
                        "{%0,%1,%2,%3},{%4,%5,%6,%7},{%8,%9},{%0,%1,%2,%3};"
                        : "+f"(c[tm][tn][0]), "+f"(c[tm][tn][1]),
                          "+f"(c[tm][tn][2]), "+f"(c[tm][tn][3])
                        : "r"(a[tm][0]), "r"(a[tm][1]), "r"(a[tm][2]), "r"(a[tm][3]),
                          "r"(b0), "r"(b1));
                }
        }
    }

    const int cm = lane >> 2, cn2 = (lane & 3) * 2;
    #pragma unroll
    for (int tm = 0; tm < 2; ++tm)
        #pragma unroll
        for (int tn = 0; tn < 4; ++tn) {
            int row0 = bm * 128 + wm * 32 + tm * 16 + cm;
            int col  = bn * 64 + wn * 32 + tn * 8 + cn2;
            float* p0 = g_pred + (size_t)row0 * PREDN + col;
            *(float2*)p0 = make_float2(c[tm][tn][0], c[tm][tn][1]);
            *(float2*)(p0 + 8 * PREDN) = make_float2(c[tm][tn][2], c[tm][tn][3]);
        }
}

// ---------------------------------------------------------------------------
// Loss: one warp per row, barrier-free. Negatives via int8 DP4A dot:
// lane's LDGs are CONTIGUOUS per 8-lane segment (1 full 128B line each).
// ---------------------------------------------------------------------------
__global__ __launch_bounds__(256, 5) void loss_kernel(const void* __restrict__ negv) {
    const int warp = threadIdx.x >> 5;
    const int lane = threadIdx.x & 31;
    const int gid  = blockIdx.x * 8 + warp;
    const int hi   = gid >> 13;
    const int n    = gid & (BT - 1);

    const int k = c_k[hi];
    const int L = 512 - k;
    const int NR = 16 * L;

    if (n >= NR) {
        if (lane == 0) g_row[gid] = 0.0f;
        return;
    }

    const int b = n / L;
    const int l = n - b * L;
    const int m = b * 512 + l;

    __shared__ unsigned syq_all[8 * 64];       // per-warp 64 words = 256 int8
    unsigned* syq = syq_all + warp * 64;

    // ---- phase 1: norm(y), pos logit (fp32) ----
    const float4* yp = (const float4*)(g_pred + (long long)m * PREDN + hi * DIM);
    const float4* zp = (const float4*)(g_allz + (long long)(m + k) * DIM);
    float4 ya = yp[lane], yb = yp[lane + 32];
    float4 za = zp[lane], zb = zp[lane + 32];
    float v1 = ya.x*ya.x + ya.y*ya.y + ya.z*ya.z + ya.w*ya.w
             + yb.x*yb.x + yb.y*yb.y + yb.z*yb.z + yb.w*yb.w;
    float v2 = ya.x*za.x + ya.y*za.y + ya.z*za.z + ya.w*za.w
             + yb.x*zb.x + yb.y*zb.y + yb.z*zb.z + yb.w*zb.w;
    v1 = warp_sum(v1);
    v2 = warp_sum(v2);
    const float invn = 1.0f / fmaxf(sqrtf(v1), 1e-12f);
    const float pos  = v2 * invn * 14.285714286f;

    // unit y quantized to int8x4 words: word w = elems [4w, 4w+4)
    syq[lane]      = pack_s8x4(ya.x*invn, ya.y*invn, ya.z*invn, ya.w*invn);
    syq[32 + lane] = pack_s8x4(yb.x*invn, yb.y*invn, yb.z*invn, yb.w*invn);
    __syncwarp();

    // lane chunks: elems [16c,16c+16) and [128+16c,+16)
    const int seg = lane >> 3;                 // 0..3
    const int c   = lane & 7;                  // 0..7
    uint4 tq0 = *(const uint4*)(syq + 4*c);
    uint4 tq1 = *(const uint4*)(syq + 32 + 4*c);

    const int is64 = g_is64;
    const long long base = ((long long)(hi * BT + n)) * NNEG;
    const int* neg32 = (const int*)negv;

    // ---- phase 2: 128 negatives, 4 per pass (8 lanes each) ----
    float ssum = 0.0f;
    #pragma unroll 4
    for (int pass = 0; pass < 32; ++pass) {
        int j = (pass << 2) + seg;
        long long o = base + j;
        int idx = neg32[is64 ? (o << 1) : o];
        const uint4* rowp = (const uint4*)(g_allzq + ((size_t)idx << 6));
        uint4 u0 = rowp[c];                    // bytes [16c,16c+16) — contiguous per segment
        uint4 u1 = rowp[c + 8];                // bytes [128+16c,+16)

        int acc = dp4a_s(u0.x, tq0.x, 0);
        acc = dp4a_s(u0.y, tq0.y, acc);
        acc = dp4a_s(u0.z, tq0.z, acc);
        acc = dp4a_s(u0.w, tq0.w, acc);
        acc = dp4a_s(u1.x, tq1.x, acc);
        acc = dp4a_s(u1.y, tq1.y, acc);
        acc = dp4a_s(u1.z, tq1.z, acc);
        acc = dp4a_s(u1.w, tq1.w, acc);

        float d = (float)acc;
        d += __shfl_xor_sync(0xffffffffu, d, 1);
        d += __shfl_xor_sync(0xffffffffu, d, 2);
        d += __shfl_xor_sync(0xffffffffu, d, 4);
        ssum += __expf(d * LSCALE);            // |logit| <= 14.3: safe
    }

    ssum += __shfl_xor_sync(0xffffffffu, ssum, 8);
    ssum += __shfl_xor_sync(0xffffffffu, ssum, 16);

    if (lane == 0) {
        float lse = logf(ssum + expf(pos));
        g_row[gid] = c_w[hi] * (lse - pos) / (float)NR;
    }
}

// ---------------------------------------------------------------------------
__global__ __launch_bounds__(256) void reduce_kernel(float* __restrict__ out) {
    __shared__ float s[256];
    float acc = 0.0f;
    for (int i = threadIdx.x; i < NH * BT; i += 256) acc += g_row[i];
    s[threadIdx.x] = acc;
    __syncthreads();
    for (int st = 128; st; st >>= 1) {
        if (threadIdx.x < st) s[threadIdx.x] += s[threadIdx.x + st];
        __syncthreads();
    }
    if (threadIdx.x == 0) out[0] = s[0];
}

// ---------------------------------------------------------------------------
extern "C" void kernel_launch(void* const* d_in, const int* in_sizes, int n_in,
                              void* d_out, int out_size) {
    const float* z_seq = (const float*)d_in[0];   // (16,512,256) f32
    const float* preds = (const float*)d_in[1];   // (3,256,256)  f32
    const void*  neg   = d_in[2];                 // (3,8192,128) int32 or int64

    __half* a16 = nullptr;  __half* w16 = nullptr;
    cudaGetSymbolAddress((void**)&a16, g_a16);
    cudaGetSymbolAddress((void**)&w16, g_w16);

    detect_kernel<<<1, 1>>>((const long long*)neg);
    norm_kernel<<<BT / 8, 256>>>(z_seq);
    predconv_kernel<<<PREDN * DIM / 4 / 256, 256>>>(preds);
    gemm16_kernel<<<dim3(PREDN / 64, BT / 128), 256>>>(a16, w16);
    loss_kernel<<<NH * BT / 8, 256>>>(neg);
    reduce_kernel<<<1, 256>>>((float*)d_out);
}

// round 15
// speedup vs baseline: 4.6604x; 1.0329x over previous
#include <cuda_runtime.h>
#include <cuda_fp16.h>

#define BT    8192          // B*T
#define DIM   256
#define NH    3
#define NNEG  128
#define PREDN (NH*DIM)      // 768

__device__ float         g_allz [BT * DIM];    // normalized z table, fp32 (8 MB) — pos logits
__device__ unsigned      g_allzq[BT * DIM / 4];// normalized z table, int8x4 (2 MB) — neg gathers
__device__ __half        g_a16  [BT * DIM];    // raw z, fp16 (4 MB) — GEMM A operand
__device__ __half        g_w16  [PREDN * DIM]; // preds, fp16 (0.4 MB) — GEMM B operand
__device__ float         g_pred [BT * PREDN];  // z_pred for all horizons (24 MB)
__device__ float         g_row  [NH * BT];     // per-row weighted losses
__device__ int           g_is64;

__constant__ int   c_k[3] = {1, 5, 21};
__constant__ float c_w[3] = {0.6004450f, 0.26852716f, 0.13102784f}; // (1/sqrt k)/tot

// logit = dot_int * (1/(127*127)) * (1/0.07)
#define LSCALE 8.857410e-4f

// ---- helpers -------------------------------------------------------------
__device__ __forceinline__ float warp_sum(float v) {
    #pragma unroll
    for (int o = 16; o; o >>= 1) v += __shfl_xor_sync(0xffffffffu, v, o);
    return v;
}
__device__ __forceinline__ int dp4a_s(unsigned a, unsigned b, int c) {
    return __dp4a((int)a, (int)b, c);
}
__device__ __forceinline__ unsigned pack_s8x4(float a, float b, float c, float d) {
    int qa = __float2int_rn(a * 127.0f);
    int qb = __float2int_rn(b * 127.0f);
    int qc = __float2int_rn(c * 127.0f);
    int qd = __float2int_rn(d * 127.0f);
    return (qa & 0xff) | ((qb & 0xff) << 8) | ((qc & 0xff) << 16) | ((qd & 0xff) << 24);
}
__device__ __forceinline__ unsigned sptr(const void* p) {
    return (unsigned)__cvta_generic_to_shared(p);
}
__device__ __forceinline__ void cp16(unsigned dst, const void* src) {
    asm volatile("cp.async.cg.shared.global [%0], [%1], 16;" :: "r"(dst), "l"(src));
}

// ---------------------------------------------------------------------------
// Parallel width detect: 32 lanes x 2 loads + ballot (was 1-thread serial).
// ---------------------------------------------------------------------------
__global__ void detect_kernel(const long long* __restrict__ neg) {
    int lane = threadIdx.x;
    unsigned long long v0 = (unsigned long long)neg[lane];
    unsigned long long v1 = (unsigned long long)neg[lane + 32];
    int bad = (v0 >= (unsigned long long)BT) || (v1 >= (unsigned long long)BT);
    unsigned mask = __ballot_sync(0xffffffffu, bad);
    if (lane == 0) g_is64 = (mask == 0u);
}

// ---------------------------------------------------------------------------
// Normalize rows -> g_allz (fp32), g_allzq (int8); raw fp16 copy -> g_a16.
// ---------------------------------------------------------------------------
__global__ __launch_bounds__(256) void norm_kernel(const float* __restrict__ z) {
    int warp = threadIdx.x >> 5;
    int lane = threadIdx.x & 31;
    int row  = blockIdx.x * 8 + warp;

    const float4* src = (const float4*)(z + (long long)row * DIM);
    float4 a = src[lane];
    float4 b = src[lane + 32];

    {
        __half2* a16 = (__half2*)(g_a16 + (long long)row * DIM);
        a16[2*lane+0]    = __floats2half2_rn(a.x, a.y);
        a16[2*lane+1]    = __floats2half2_rn(a.z, a.w);
        a16[64+2*lane+0] = __floats2half2_rn(b.x, b.y);
        a16[64+2*lane+1] = __floats2half2_rn(b.z, b.w);
    }

    float s = a.x*a.x + a.y*a.y + a.z*a.z + a.w*a.w
            + b.x*b.x + b.y*b.y + b.z*b.z + b.w*b.w;
    s = warp_sum(s);
    float inv = 1.0f / fmaxf(sqrtf(s), 1e-12f);

    a.x *= inv; a.y *= inv; a.z *= inv; a.w *= inv;
    b.x *= inv; b.y *= inv; b.z *= inv; b.w *= inv;

    float4* dst = (float4*)(g_allz + (long long)row * DIM);
    dst[lane]      = a;
    dst[lane + 32] = b;

    unsigned* rq = g_allzq + (long long)row * (DIM / 4);
    rq[lane]      = pack_s8x4(a.x, a.y, a.z, a.w);
    rq[32 + lane] = pack_s8x4(b.x, b.y, b.z, b.w);
}

// ---------------------------------------------------------------------------
// preds f32 -> f16 (196608 elems, 4 per thread).
// ---------------------------------------------------------------------------
__global__ __launch_bounds__(256) void predconv_kernel(const float* __restrict__ w) {
    int i = blockIdx.x * 256 + threadIdx.x;
    float4 v = *((const float4*)w + i);
    __half2* out = (__half2*)g_w16 + 2 * i;
    out[0] = __floats2half2_rn(v.x, v.y);
    out[1] = __floats2half2_rn(v.z, v.w);
}

// ---------------------------------------------------------------------------
// HMMA GEMM, 2-stage cp.async pipeline.
// BM=128, BN=64, BK=32; 8 warps (4x2); warp tile 32x32 = 2x4 m16n8k16.
// ---------------------------------------------------------------------------
#define NKT (DIM / 32)      // 8 K-steps

__global__ __launch_bounds__(256) void gemm16_kernel(const __half* __restrict__ A16,
                                                     const __half* __restrict__ W16) {
    __shared__ __half As[2][128 * 40];
    __shared__ __half Bs[2][64 * 40];

    const int tid  = threadIdx.x;
    const int lane = tid & 31, warp = tid >> 5;
    const int bn = blockIdx.x, bm = blockIdx.y;
    const int wm = warp >> 1, wn = warp & 1;

    float c[2][4][4];
    #pragma unroll
    for (int i = 0; i < 2; ++i)
        #pragma unroll
        for (int j = 0; j < 4; ++j)
            #pragma unroll
            for (int q = 0; q < 4; ++q) c[i][j][q] = 0.0f;

    const __half* Ab = A16 + (size_t)(bm * 128) * DIM;
    const __half* Wb = W16 + (size_t)(bn * 64)  * DIM;

    // per-thread load geometry (same for every stage)
    const int a_r0 = tid >> 2,        a_q = tid & 3;         // +64 rows second chunk
    const int b_r  = tid >> 2,        b_q = tid & 3;

    const int a_row = wm * 32 + (lane & 15);
    const int a_col = (lane >> 4) * 8;
    const int b_row = wn * 32 + (lane & 7) + ((lane >> 4) << 3);
    const int b_col = ((lane >> 3) & 1) * 8;

    // issue loads for K-step kt into stage st
    auto issue = [&](int kt, int st) {
        int k0 = kt * 32;
        cp16(sptr(&As[st][a_r0 * 40 + a_q * 8]),        Ab + a_r0 * DIM + k0 + a_q * 8);
        cp16(sptr(&As[st][(a_r0 + 64) * 40 + a_q * 8]), Ab + (a_r0 + 64) * DIM + k0 + a_q * 8);
        cp16(sptr(&Bs[st][b_r * 40 + b_q * 8]),         Wb + b_r * DIM + k0 + b_q * 8);
    };

    issue(0, 0);
    asm volatile("cp.async.commit_group;");

    for (int kt = 0; kt < NKT; ++kt) {
        const int cur = kt & 1;
        if (kt + 1 < NKT) issue(kt + 1, cur ^ 1);
        asm volatile("cp.async.commit_group;");
        asm volatile("cp.async.wait_group 1;");
        __syncthreads();

        #pragma unroll
        for (int ks = 0; ks < 32; ks += 16) {
            unsigned a[2][4], bfr[2][4];
            #pragma unroll
            for (int tm = 0; tm < 2; ++tm) {
                unsigned addr = sptr(&As[cur][(a_row + tm * 16) * 40 + a_col + ks]);
                asm volatile("ldmatrix.sync.aligned.m8n8.x4.shared.b16 {%0,%1,%2,%3},[%4];"
                    : "=r"(a[tm][0]), "=r"(a[tm][1]), "=r"(a[tm][2]), "=r"(a[tm][3])
                    : "r"(addr));
            }
            #pragma unroll
            for (int g = 0; g < 2; ++g) {
                unsigned addr = sptr(&Bs[cur][(b_row + g * 16) * 40 + b_col + ks]);
                asm volatile("ldmatrix.sync.aligned.m8n8.x4.shared.b16 {%0,%1,%2,%3},[%4];"
                    : "=r"(bfr[g][0]), "=r"(bfr[g][1]), "=r"(bfr[g][2]), "=r"(bfr[g][3])
                    : "r"(addr));
            }
            #pragma unroll
            for (int tm = 0; tm < 2; ++tm)
                #pragma unroll
                for (int tn = 0; tn < 4; ++tn) {
                    unsigned b0 = bfr[tn >> 1][(tn & 1) * 2 + 0];
                    unsigned b1 = bfr[tn >> 1][(tn & 1) * 2 + 1];
                    asm volatile(
                        "mma.sync.aligned.m16n8k16.row.col.f32.f16.f16.f32 "
                        "{%0,%1,%2,%3},{%4,%5,%6,%7},{%8,%9},{%0,%1,%2,%3};"
                        : "+f"(c[tm][tn][0]), "+f"(c[tm][tn][1]),
                          "+f"(c[tm][tn][2]), "+f"(c[tm][tn][3])
                        : "r"(a[tm][0]), "r"(a[tm][1]), "r"(a[tm][2]), "r"(a[tm][3]),
                          "r"(b0), "r"(b1));
                }
        }
        __syncthreads();   // all warps done with stage cur before it is re-filled
    }

    const int cm = lane >> 2, cn2 = (lane & 3) * 2;
    #pragma unroll
    for (int tm = 0; tm < 2; ++tm)
        #pragma unroll
        for (int tn = 0; tn < 4; ++tn) {
            int row0 = bm * 128 + wm * 32 + tm * 16 + cm;
            int col  = bn * 64 + wn * 32 + tn * 8 + cn2;
            float* p0 = g_pred + (size_t)row0 * PREDN + col;
            *(float2*)p0 = make_float2(c[tm][tn][0], c[tm][tn][1]);
            *(float2*)(p0 + 8 * PREDN) = make_float2(c[tm][tn][2], c[tm][tn][3]);
        }
}

// ---------------------------------------------------------------------------
// Loss: one warp per row, barrier-free, int8 DP4A (unchanged from R14 win).
// ---------------------------------------------------------------------------
__global__ __launch_bounds__(256, 5) void loss_kernel(const void* __restrict__ negv) {
    const int warp = threadIdx.x >> 5;
    const int lane = threadIdx.x & 31;
    const int gid  = blockIdx.x * 8 + warp;
    const int hi   = gid >> 13;
    const int n    = gid & (BT - 1);

    const int k = c_k[hi];
    const int L = 512 - k;
    const int NR = 16 * L;

    if (n >= NR) {
        if (lane == 0) g_row[gid] = 0.0f;
        return;
    }

    const int b = n / L;
    const int l = n - b * L;
    const int m = b * 512 + l;

    __shared__ unsigned syq_all[8 * 64];
    unsigned* syq = syq_all + warp * 64;

    const float4* yp = (const float4*)(g_pred + (long long)m * PREDN + hi * DIM);
    const float4* zp = (const float4*)(g_allz + (long long)(m + k) * DIM);
    float4 ya = yp[lane], yb = yp[lane + 32];
    float4 za = zp[lane], zb = zp[lane + 32];
    float v1 = ya.x*ya.x + ya.y*ya.y + ya.z*ya.z + ya.w*ya.w
             + yb.x*yb.x + yb.y*yb.y + yb.z*yb.z + yb.w*yb.w;
    float v2 = ya.x*za.x + ya.y*za.y + ya.z*za.z + ya.w*za.w
             + yb.x*zb.x + yb.y*zb.y + yb.z*zb.z + yb.w*zb.w;
    v1 = warp_sum(v1);
    v2 = warp_sum(v2);
    const float invn = 1.0f / fmaxf(sqrtf(v1), 1e-12f);
    const float pos  = v2 * invn * 14.285714286f;

    syq[lane]      = pack_s8x4(ya.x*invn, ya.y*invn, ya.z*invn, ya.w*invn);
    syq[32 + lane] = pack_s8x4(yb.x*invn, yb.y*invn, yb.z*invn, yb.w*invn);
    __syncwarp();

    const int seg = lane >> 3;
    const int c   = lane & 7;
    uint4 tq0 = *(const uint4*)(syq + 4*c);
    uint4 tq1 = *(const uint4*)(syq + 32 + 4*c);

    const int is64 = g_is64;
    const long long base = ((long long)(hi * BT + n)) * NNEG;
    const int* neg32 = (const int*)negv;

    float ssum = 0.0f;
    #pragma unroll 4
    for (int pass = 0; pass < 32; ++pass) {
        int j = (pass << 2) + seg;
        long long o = base + j;
        int idx = neg32[is64 ? (o << 1) : o];
        const uint4* rowp = (const uint4*)(g_allzq + ((size_t)idx << 6));
        uint4 u0 = rowp[c];
        uint4 u1 = rowp[c + 8];

        int acc = dp4a_s(u0.x, tq0.x, 0);
        acc = dp4a_s(u0.y, tq0.y, acc);
        acc = dp4a_s(u0.z, tq0.z, acc);
        acc = dp4a_s(u0.w, tq0.w, acc);
        acc = dp4a_s(u1.x, tq1.x, acc);
        acc = dp4a_s(u1.y, tq1.y, acc);
        acc = dp4a_s(u1.z, tq1.z, acc);
        acc = dp4a_s(u1.w, tq1.w, acc);

        float d = (float)acc;
        d += __shfl_xor_sync(0xffffffffu, d, 1);
        d += __shfl_xor_sync(0xffffffffu, d, 2);
        d += __shfl_xor_sync(0xffffffffu, d, 4);
        ssum += __expf(d * LSCALE);
    }

    ssum += __shfl_xor_sync(0xffffffffu, ssum, 8);
    ssum += __shfl_xor_sync(0xffffffffu, ssum, 16);

    if (lane == 0) {
        float lse = logf(ssum + expf(pos));
        g_row[gid] = c_w[hi] * (lse - pos) / (float)NR;
    }
}

// ---------------------------------------------------------------------------
__global__ __launch_bounds__(256) void reduce_kernel(float* __restrict__ out) {
    __shared__ float s[256];
    float acc = 0.0f;
    for (int i = threadIdx.x; i < NH * BT; i += 256) acc += g_row[i];
    s[threadIdx.x] = acc;
    __syncthreads();
    for (int st = 128; st; st >>= 1) {
        if (threadIdx.x < st) s[threadIdx.x] += s[threadIdx.x + st];
        __syncthreads();
    }
    if (threadIdx.x == 0) out[0] = s[0];
}

// ---------------------------------------------------------------------------
extern "C" void kernel_launch(void* const* d_in, const int* in_sizes, int n_in,
                              void* d_out, int out_size) {
    const float* z_seq = (const float*)d_in[0];   // (16,512,256) f32
    const float* preds = (const float*)d_in[1];   // (3,256,256)  f32
    const void*  neg   = d_in[2];                 // (3,8192,128) int32 or int64

    __half* a16 = nullptr;  __half* w16 = nullptr;
    cudaGetSymbolAddress((void**)&a16, g_a16);
    cudaGetSymbolAddress((void**)&w16, g_w16);

    detect_kernel<<<1, 32>>>((const long long*)neg);
    norm_kernel<<<BT / 8, 256>>>(z_seq);
    predconv_kernel<<<PREDN * DIM / 4 / 256, 256>>>(preds);
    gemm16_kernel<<<dim3(PREDN / 64, BT / 128), 256>>>(a16, w16);
    loss_kernel<<<NH * BT / 8, 256>>>(neg);
    reduce_kernel<<<1, 256>>>((float*)d_out);
}